// round 4
// baseline (speedup 1.0000x reference)
#include <cuda_runtime.h>
#include <cuda_bf16.h>
#include <math.h>

// ---------------------------------------------------------------------------
// Problem constants (fixed shapes)
// ---------------------------------------------------------------------------
#define NWIN   4096
#define W      64
#define DIM    256
#define H      8
#define DH     32
#define HID    1024
#define M_ACT  2048
#define TOK    (M_ACT * W)        // 131072 active tokens
#define ROWS_ALL (NWIN * W)       // 262144 total rows
#define QKVC   (3 * DIM)          // 768

// ---------------------------------------------------------------------------
// Scratch (device globals; allocation inside kernel_launch is forbidden)
// ---------------------------------------------------------------------------
__device__ float g_qkv [(size_t)TOK * QKVC];   // 402 MB
__device__ float g_attn[(size_t)TOK * DIM];    // 134 MB
__device__ float g_h   [(size_t)TOK * DIM];    // 134 MB
__device__ float g_h2  [(size_t)TOK * DIM];    // 134 MB
__device__ float g_hid [(size_t)TOK * HID];    // 536 MB
__device__ int   g_rowmap[TOK];

// ---------------------------------------------------------------------------
// Row map: active token t -> global row index in X
// ---------------------------------------------------------------------------
__global__ void rowmap_kernel(const int* __restrict__ index) {
    int t = blockIdx.x * blockDim.x + threadIdx.x;
    if (t < TOK) g_rowmap[t] = index[t >> 6] * W + (t & (W - 1));
}

// ---------------------------------------------------------------------------
// LayerNorm over last dim (256). One warp per row, 8 rows per block.
// ---------------------------------------------------------------------------
__global__ __launch_bounds__(256)
void ln_kernel(const float* __restrict__ in, float* __restrict__ out,
               const float* __restrict__ gam, const float* __restrict__ bet,
               int nrows)
{
    int warp = threadIdx.x >> 5;
    int lane = threadIdx.x & 31;
    int row  = blockIdx.x * 8 + warp;
    if (row >= nrows) return;

    const float* p = in + (size_t)row * DIM;
    float4 v0 = *(const float4*)(p + lane * 4);
    float4 v1 = *(const float4*)(p + 128 + lane * 4);

    float s = v0.x + v0.y + v0.z + v0.w + v1.x + v1.y + v1.z + v1.w;
    #pragma unroll
    for (int o = 16; o > 0; o >>= 1) s += __shfl_xor_sync(0xffffffffu, s, o);
    float mu = s * (1.0f / 256.0f);

    float d0 = v0.x - mu, d1 = v0.y - mu, d2 = v0.z - mu, d3 = v0.w - mu;
    float d4 = v1.x - mu, d5 = v1.y - mu, d6 = v1.z - mu, d7 = v1.w - mu;
    float vs = d0*d0 + d1*d1 + d2*d2 + d3*d3 + d4*d4 + d5*d5 + d6*d6 + d7*d7;
    #pragma unroll
    for (int o = 16; o > 0; o >>= 1) vs += __shfl_xor_sync(0xffffffffu, vs, o);
    float inv = rsqrtf(vs * (1.0f / 256.0f) + 1e-5f);

    float4 g0 = *(const float4*)(gam + lane * 4);
    float4 g1 = *(const float4*)(gam + 128 + lane * 4);
    float4 b0 = *(const float4*)(bet + lane * 4);
    float4 b1 = *(const float4*)(bet + 128 + lane * 4);

    float4 o0, o1;
    o0.x = d0 * inv * g0.x + b0.x;  o0.y = d1 * inv * g0.y + b0.y;
    o0.z = d2 * inv * g0.z + b0.z;  o0.w = d3 * inv * g0.w + b0.w;
    o1.x = d4 * inv * g1.x + b1.x;  o1.y = d5 * inv * g1.y + b1.y;
    o1.z = d6 * inv * g1.z + b1.z;  o1.w = d7 * inv * g1.w + b1.w;

    float* q = out + (size_t)row * DIM;
    *(float4*)(q + lane * 4) = o0;
    *(float4*)(q + 128 + lane * 4) = o1;
}

// ---------------------------------------------------------------------------
// SGEMM: C[M,N] = A[M,K] @ B[K,N] + bias, with optional epilogues.
//   EPI 0: bias only
//   EPI 1: bias + exact GELU
//   EPI 2: bias + residual add
// Optional gather on A rows (rowmapA), on residual rows (rowmapRes),
// and scatter on C rows (rowmapC). Row stride for gathered/scattered rows
// is K (for A) resp. Ncols (for Res/C).
// Tiles: 128x128x8, 256 threads, 8x8 register tile.
// ---------------------------------------------------------------------------
#define BM 128
#define BN 128
#define BK 8
#define TM 8
#define TN 8

template<int EPI>
__global__ __launch_bounds__(256)
void gemm_kernel(const float* __restrict__ A, const int* __restrict__ rowmapA,
                 const float* __restrict__ B, const float* __restrict__ bias,
                 float* __restrict__ C, const int* __restrict__ rowmapC,
                 const float* __restrict__ Res, const int* __restrict__ rowmapRes,
                 int Ncols, int K)
{
    __shared__ __align__(16) float As[BK][BM];
    __shared__ __align__(16) float Bs[BK][BN];

    const int tid = threadIdx.x;
    const int rowBase = blockIdx.y * BM;
    const int colBase = blockIdx.x * BN;

    // A tile loader: thread -> (row = tid/2, kcol = (tid&1)*4), one float4
    const int aRow = tid >> 1;
    const int aCol = (tid & 1) * 4;
    const int gRowA = rowBase + aRow;
    const size_t arow = rowmapA ? (size_t)rowmapA[gRowA] : (size_t)gRowA;
    const float* Aptr = A + arow * (size_t)K + aCol;

    // B tile loader: thread -> (krow = tid/32, col = (tid&31)*4), one float4
    const int bRow = tid >> 5;
    const int bCol = (tid & 31) * 4;
    const float* Bptr = B + (size_t)bRow * Ncols + colBase + bCol;

    float acc[TM][TN];
    #pragma unroll
    for (int i = 0; i < TM; i++)
        #pragma unroll
        for (int j = 0; j < TN; j++) acc[i][j] = 0.0f;

    const int tx = tid & 15;
    const int ty = tid >> 4;
    const int tRow = ty * TM;
    const int tCol = tx * TN;

    for (int k0 = 0; k0 < K; k0 += BK) {
        float4 a4 = *(const float4*)(Aptr + k0);
        As[aCol + 0][aRow] = a4.x;
        As[aCol + 1][aRow] = a4.y;
        As[aCol + 2][aRow] = a4.z;
        As[aCol + 3][aRow] = a4.w;
        *(float4*)&Bs[bRow][bCol] = *(const float4*)(Bptr + (size_t)k0 * Ncols);
        __syncthreads();

        #pragma unroll
        for (int kk = 0; kk < BK; kk++) {
            float a[TM], b[TN];
            #pragma unroll
            for (int i = 0; i < TM; i += 4)
                *(float4*)&a[i] = *(const float4*)&As[kk][tRow + i];
            #pragma unroll
            for (int j = 0; j < TN; j += 4)
                *(float4*)&b[j] = *(const float4*)&Bs[kk][tCol + j];
            #pragma unroll
            for (int i = 0; i < TM; i++)
                #pragma unroll
                for (int j = 0; j < TN; j++)
                    acc[i][j] += a[i] * b[j];
        }
        __syncthreads();
    }

    // Epilogue
    float4 bia0 = *(const float4*)(bias + colBase + tCol);
    float4 bia1 = *(const float4*)(bias + colBase + tCol + 4);
    float bi[TN] = {bia0.x, bia0.y, bia0.z, bia0.w, bia1.x, bia1.y, bia1.z, bia1.w};

    #pragma unroll
    for (int i = 0; i < TM; i++) {
        const int gr = rowBase + tRow + i;
        const size_t crow = rowmapC ? (size_t)rowmapC[gr] : (size_t)gr;
        float* Cp = C + crow * (size_t)Ncols + colBase + tCol;

        float r[TN];
        if (EPI == 2) {
            const size_t rrow = rowmapRes ? (size_t)rowmapRes[gr] : (size_t)gr;
            const float* Rp = Res + rrow * (size_t)Ncols + colBase + tCol;
            float4 r0 = *(const float4*)(Rp);
            float4 r1 = *(const float4*)(Rp + 4);
            r[0]=r0.x; r[1]=r0.y; r[2]=r0.z; r[3]=r0.w;
            r[4]=r1.x; r[5]=r1.y; r[6]=r1.z; r[7]=r1.w;
        }

        float v[TN];
        #pragma unroll
        for (int j = 0; j < TN; j++) {
            float t = acc[i][j] + bi[j];
            if (EPI == 1) t = 0.5f * t * (1.0f + erff(t * 0.70710678118654752f));
            if (EPI == 2) t += r[j];
            v[j] = t;
        }
        *(float4*)(Cp)     = make_float4(v[0], v[1], v[2], v[3]);
        *(float4*)(Cp + 4) = make_float4(v[4], v[5], v[6], v[7]);
    }
}

// ---------------------------------------------------------------------------
// Attention: one block per (window m, head h). 64 threads, one query row each.
// K,V staged in smem (coalesced); Q read direct (L1). S kept in registers.
// ---------------------------------------------------------------------------
__global__ __launch_bounds__(64)
void attn_kernel(const float* __restrict__ qkv, float* __restrict__ attn_out)
{
    const int m = blockIdx.x >> 3;
    const int h = blockIdx.x & 7;
    const int tid = threadIdx.x;

    __shared__ __align__(16) float Ks[W * DH];
    __shared__ __align__(16) float Vs[W * DH];

    const float* base = qkv + (size_t)m * W * QKVC + h * (3 * DH);

    // Cooperative load of K and V (each 64x32 fp32, rows of 128B -> coalesced)
    for (int i = tid * 4; i < W * DH; i += 64 * 4) {
        const int row = i >> 5, col = i & 31;
        const float* rp = base + (size_t)row * QKVC;
        *(float4*)(Ks + i) = *(const float4*)(rp + DH + col);
        *(float4*)(Vs + i) = *(const float4*)(rp + 2 * DH + col);
    }
    __syncthreads();

    const int w = tid;
    const float* qp = base + (size_t)w * QKVC;
    float q[DH];
    #pragma unroll
    for (int d = 0; d < DH; d += 4)
        *(float4*)&q[d] = *(const float4*)(qp + d);

    const float scale = 0.17677669529663687f; // 1/sqrt(32)

    float S[W];
    #pragma unroll
    for (int j = 0; j < W; j++) {
        float s0 = 0.f, s1 = 0.f, s2 = 0.f, s3 = 0.f;
        #pragma unroll
        for (int d = 0; d < DH; d += 4) {
            float4 k4 = *(const float4*)&Ks[j * DH + d];
            s0 += q[d]     * k4.x;
            s1 += q[d + 1] * k4.y;
            s2 += q[d + 2] * k4.z;
            s3 += q[d + 3] * k4.w;
        }
        S[j] = (s0 + s1 + s2 + s3) * scale;
    }

    // softmax over k
    float mx = -1e30f;
    #pragma unroll
    for (int j = 0; j < W; j++) mx = fmaxf(mx, S[j]);
    float sum = 0.f;
    #pragma unroll
    for (int j = 0; j < W; j++) { S[j] = expf(S[j] - mx); sum += S[j]; }
    const float inv = 1.0f / sum;
    #pragma unroll
    for (int j = 0; j < W; j++) S[j] *= inv;

    // O = P @ V
    float o[DH];
    #pragma unroll
    for (int d = 0; d < DH; d++) o[d] = 0.f;
    #pragma unroll
    for (int j = 0; j < W; j++) {
        const float p = S[j];
        #pragma unroll
        for (int d = 0; d < DH; d += 4) {
            float4 v4 = *(const float4*)&Vs[j * DH + d];
            o[d]     += p * v4.x;
            o[d + 1] += p * v4.y;
            o[d + 2] += p * v4.z;
            o[d + 3] += p * v4.w;
        }
    }

    float* op = attn_out + ((size_t)m * W + w) * DIM + h * DH;
    #pragma unroll
    for (int d = 0; d < DH; d += 4)
        *(float4*)(op + d) = make_float4(o[d], o[d+1], o[d+2], o[d+3]);
}

// ---------------------------------------------------------------------------
// Launch
// ---------------------------------------------------------------------------
extern "C" void kernel_launch(void* const* d_in, const int* in_sizes, int n_in,
                              void* d_out, int out_size)
{
    // metadata order: x, index, [M], norm1_g, norm1_b, qkv_w, qkv_b,
    //                 proj_w, proj_b, norm2_g, norm2_b, fc1_w, fc1_b, fc2_w, fc2_b
    int k = 0;
    const float* x      = (const float*)d_in[k++];
    const int*   index  = (const int*)  d_in[k++];
    if (n_in >= 15) k++;  // skip scalar M slot if present
    const float* n1g    = (const float*)d_in[k++];
    const float* n1b    = (const float*)d_in[k++];
    const float* qkv_w  = (const float*)d_in[k++];
    const float* qkv_b  = (const float*)d_in[k++];
    const float* proj_w = (const float*)d_in[k++];
    const float* proj_b = (const float*)d_in[k++];
    const float* n2g    = (const float*)d_in[k++];
    const float* n2b    = (const float*)d_in[k++];
    const float* fc1_w  = (const float*)d_in[k++];
    const float* fc1_b  = (const float*)d_in[k++];
    const float* fc2_w  = (const float*)d_in[k++];
    const float* fc2_b  = (const float*)d_in[k++];

    float* X = (float*)d_out;

    float *p_qkv, *p_attn, *p_h, *p_h2, *p_hid;
    int *p_rowmap;
    cudaGetSymbolAddress((void**)&p_qkv,    g_qkv);
    cudaGetSymbolAddress((void**)&p_attn,   g_attn);
    cudaGetSymbolAddress((void**)&p_h,      g_h);
    cudaGetSymbolAddress((void**)&p_h2,     g_h2);
    cudaGetSymbolAddress((void**)&p_hid,    g_hid);
    cudaGetSymbolAddress((void**)&p_rowmap, g_rowmap);

    // 1) LayerNorm1 over ALL rows -> X (d_out)
    ln_kernel<<<ROWS_ALL / 8, 256>>>(x, X, n1g, n1b, ROWS_ALL);

    // 2) Row map for active tokens
    rowmap_kernel<<<TOK / 256, 256>>>(index);

    // 3) QKV GEMM: gather(X) @ qkv_w + qkv_b -> g_qkv   [131072 x 768]
    gemm_kernel<0><<<dim3(QKVC / BN, TOK / BM), 256>>>(
        X, p_rowmap, qkv_w, qkv_b, p_qkv, nullptr, nullptr, nullptr, QKVC, DIM);

    // 4) Attention -> g_attn  [131072 x 256]
    attn_kernel<<<M_ACT * H, 64>>>(p_qkv, p_attn);

    // 5) Proj GEMM + shortcut (gathered X) -> g_h
    gemm_kernel<2><<<dim3(DIM / BN, TOK / BM), 256>>>(
        p_attn, nullptr, proj_w, proj_b, p_h, nullptr, X, p_rowmap, DIM, DIM);

    // 6) LayerNorm2: g_h -> g_h2
    ln_kernel<<<TOK / 8, 256>>>(p_h, p_h2, n2g, n2b, TOK);

    // 7) FC1 GEMM + GELU -> g_hid  [131072 x 1024]
    gemm_kernel<1><<<dim3(HID / BN, TOK / BM), 256>>>(
        p_h2, nullptr, fc1_w, fc1_b, p_hid, nullptr, nullptr, nullptr, HID, DIM);

    // 8) FC2 GEMM + residual(g_h), scatter rows into d_out
    gemm_kernel<2><<<dim3(DIM / BN, TOK / BM), 256>>>(
        p_hid, nullptr, fc2_w, fc2_b, X, p_rowmap, p_h, nullptr, DIM, HID);

    (void)in_sizes; (void)out_size;
}

// round 5
// speedup vs baseline: 2.3670x; 2.3670x over previous
#include <cuda_runtime.h>
#include <cuda_bf16.h>
#include <math.h>
#include <stdint.h>

// ---------------------------------------------------------------------------
// Problem constants (fixed shapes)
// ---------------------------------------------------------------------------
#define NWIN   4096
#define W      64
#define DIM    256
#define H      8
#define DH     32
#define HID    1024
#define M_ACT  2048
#define TOK    (M_ACT * W)        // 131072 active tokens
#define ROWS_ALL (NWIN * W)       // 262144 total rows
#define QKVC   (3 * DIM)          // 768

// ---------------------------------------------------------------------------
// Scratch (device globals; allocation inside kernel_launch is forbidden)
// ---------------------------------------------------------------------------
__device__ float g_qkv [(size_t)TOK * QKVC];   // 402 MB
__device__ float g_attn[(size_t)TOK * DIM];    // 134 MB
__device__ float g_h   [(size_t)TOK * DIM];    // 134 MB
__device__ float g_h2  [(size_t)TOK * DIM];    // 134 MB
__device__ float g_hid [(size_t)TOK * HID];    // 536 MB
__device__ int   g_rowmap[TOK];

// tf32-rounded weight copies (concatenated)
#define WOFF_QKV  0
#define WOFF_PROJ (DIM * QKVC)                       // 196608
#define WOFF_FC1  (WOFF_PROJ + DIM * DIM)            // 262144
#define WOFF_FC2  (WOFF_FC1 + DIM * HID)             // 524288
#define WTOTAL    (WOFF_FC2 + HID * DIM)             // 786432
__device__ float g_wr[WTOTAL];

// ---------------------------------------------------------------------------
// tf32 round-to-nearest helper
// ---------------------------------------------------------------------------
__device__ __forceinline__ float rtf32(float x) {
    uint32_t u;
    asm("cvt.rna.tf32.f32 %0, %1;" : "=r"(u) : "f"(x));
    return __uint_as_float(u);
}

// ---------------------------------------------------------------------------
// Round-copy for weights (fp32 -> tf32-rounded fp32)
// ---------------------------------------------------------------------------
__global__ void round_copy_kernel(const float* __restrict__ src,
                                  float* __restrict__ dst, int n)
{
    int i = (blockIdx.x * blockDim.x + threadIdx.x) * 4;
    if (i < n) {
        float4 v = *(const float4*)(src + i);
        v.x = rtf32(v.x); v.y = rtf32(v.y); v.z = rtf32(v.z); v.w = rtf32(v.w);
        *(float4*)(dst + i) = v;
    }
}

// ---------------------------------------------------------------------------
// Row map: active token t -> global row index in X
// ---------------------------------------------------------------------------
__global__ void rowmap_kernel(const int* __restrict__ index) {
    int t = blockIdx.x * blockDim.x + threadIdx.x;
    if (t < TOK) g_rowmap[t] = index[t >> 6] * W + (t & (W - 1));
}

// ---------------------------------------------------------------------------
// LayerNorm over last dim (256). One warp per row, 8 rows per block.
// RND: round outputs to tf32 (they feed a tf32 GEMM A operand).
// ---------------------------------------------------------------------------
template<bool RND>
__global__ __launch_bounds__(256)
void ln_kernel(const float* __restrict__ in, float* __restrict__ out,
               const float* __restrict__ gam, const float* __restrict__ bet,
               int nrows)
{
    int warp = threadIdx.x >> 5;
    int lane = threadIdx.x & 31;
    int row  = blockIdx.x * 8 + warp;
    if (row >= nrows) return;

    const float* p = in + (size_t)row * DIM;
    float4 v0 = *(const float4*)(p + lane * 4);
    float4 v1 = *(const float4*)(p + 128 + lane * 4);

    float s = v0.x + v0.y + v0.z + v0.w + v1.x + v1.y + v1.z + v1.w;
    #pragma unroll
    for (int o = 16; o > 0; o >>= 1) s += __shfl_xor_sync(0xffffffffu, s, o);
    float mu = s * (1.0f / 256.0f);

    float d0 = v0.x - mu, d1 = v0.y - mu, d2 = v0.z - mu, d3 = v0.w - mu;
    float d4 = v1.x - mu, d5 = v1.y - mu, d6 = v1.z - mu, d7 = v1.w - mu;
    float vs = d0*d0 + d1*d1 + d2*d2 + d3*d3 + d4*d4 + d5*d5 + d6*d6 + d7*d7;
    #pragma unroll
    for (int o = 16; o > 0; o >>= 1) vs += __shfl_xor_sync(0xffffffffu, vs, o);
    float inv = rsqrtf(vs * (1.0f / 256.0f) + 1e-5f);

    float4 g0 = *(const float4*)(gam + lane * 4);
    float4 g1 = *(const float4*)(gam + 128 + lane * 4);
    float4 b0 = *(const float4*)(bet + lane * 4);
    float4 b1 = *(const float4*)(bet + 128 + lane * 4);

    float4 o0, o1;
    o0.x = d0 * inv * g0.x + b0.x;  o0.y = d1 * inv * g0.y + b0.y;
    o0.z = d2 * inv * g0.z + b0.z;  o0.w = d3 * inv * g0.w + b0.w;
    o1.x = d4 * inv * g1.x + b1.x;  o1.y = d5 * inv * g1.y + b1.y;
    o1.z = d6 * inv * g1.z + b1.z;  o1.w = d7 * inv * g1.w + b1.w;

    if (RND) {
        o0.x = rtf32(o0.x); o0.y = rtf32(o0.y); o0.z = rtf32(o0.z); o0.w = rtf32(o0.w);
        o1.x = rtf32(o1.x); o1.y = rtf32(o1.y); o1.z = rtf32(o1.z); o1.w = rtf32(o1.w);
    }

    float* q = out + (size_t)row * DIM;
    *(float4*)(q + lane * 4) = o0;
    *(float4*)(q + 128 + lane * 4) = o1;
}

// ---------------------------------------------------------------------------
// tf32 tensor-core GEMM: C[M,N] = A[M,K] @ B[K,N] + bias, epilogues:
//   EPI 0: bias only
//   EPI 1: bias + exact GELU (+ tf32 round: feeds next GEMM A)
//   EPI 2: bias + residual add
// Optional gather on A rows, residual rows; scatter on C rows.
// Tiles: 128x128x16, 256 threads (8 warps, 4x2), warp tile 32x64,
// mma.sync.m16n8k8 tf32, cp.async double buffering.
// ---------------------------------------------------------------------------
#define BM 128
#define BN 128
#define BK 16
#define ASTR 20    // floats per As row (BK + 4) -> conflict-free A frag LDS
#define BSTR 136   // floats per Bs row (BN + 8) -> conflict-free B frag LDS

__device__ __forceinline__ void cp_async16(void* smem, const void* gmem) {
    uint32_t s = (uint32_t)__cvta_generic_to_shared(smem);
    asm volatile("cp.async.cg.shared.global [%0], [%1], 16;\n" :: "r"(s), "l"(gmem));
}
__device__ __forceinline__ void cp_commit() {
    asm volatile("cp.async.commit_group;\n");
}
__device__ __forceinline__ void cp_wait_all() {
    asm volatile("cp.async.wait_group 0;\n");
}

__device__ __forceinline__ void mma_tf32(float* c, const uint32_t* a, const uint32_t* b) {
    asm volatile(
        "mma.sync.aligned.m16n8k8.row.col.f32.tf32.tf32.f32 "
        "{%0,%1,%2,%3},{%4,%5,%6,%7},{%8,%9},{%0,%1,%2,%3};\n"
        : "+f"(c[0]), "+f"(c[1]), "+f"(c[2]), "+f"(c[3])
        : "r"(a[0]), "r"(a[1]), "r"(a[2]), "r"(a[3]), "r"(b[0]), "r"(b[1]));
}

template<int EPI>
__global__ __launch_bounds__(256)
void gemm_tf32(const float* __restrict__ A, const int* __restrict__ rowmapA,
               const float* __restrict__ B, const float* __restrict__ bias,
               float* __restrict__ C, const int* __restrict__ rowmapC,
               const float* __restrict__ Res, const int* __restrict__ rowmapRes,
               int Ncols, int K)
{
    __shared__ __align__(16) float As[2][BM * ASTR];
    __shared__ __align__(16) float Bs[2][BK * BSTR];

    const int tid = threadIdx.x;
    const int rowBase = blockIdx.y * BM;
    const int colBase = blockIdx.x * BN;

    // A loader: row r = tid>>1, k-offset kc = (tid&1)*8, two 16B chunks
    const int ar  = tid >> 1;
    const int akc = (tid & 1) * 8;
    const int gRowA = rowBase + ar;
    const size_t arowIdx = rowmapA ? (size_t)rowmapA[gRowA] : (size_t)gRowA;
    const float* Aptr = A + arowIdx * (size_t)K + akc;

    // B loader: rows (tid>>5) and (tid>>5)+8, col chunk (tid&31)*4
    const int bkr = tid >> 5;
    const int bc  = (tid & 31) * 4;
    const float* Bptr = B + (size_t)bkr * Ncols + colBase + bc;

    const int warp  = tid >> 5;
    const int lane  = tid & 31;
    const int warpM = warp >> 1;    // 0..3, 32 rows each
    const int warpN = warp & 1;     // 0..1, 64 cols each
    const int grp   = lane >> 2;
    const int tig   = lane & 3;

    float acc[2][8][4];
    #pragma unroll
    for (int mt = 0; mt < 2; mt++)
        #pragma unroll
        for (int nt = 0; nt < 8; nt++)
            #pragma unroll
            for (int j = 0; j < 4; j++) acc[mt][nt][j] = 0.0f;

    const int KT = K / BK;

    auto issue = [&](int kt, int s) {
        const float* ap = Aptr + kt * BK;
        cp_async16(&As[s][ar * ASTR + akc],     ap);
        cp_async16(&As[s][ar * ASTR + akc + 4], ap + 4);
        const float* bp = Bptr + (size_t)kt * BK * Ncols;
        cp_async16(&Bs[s][bkr * BSTR + bc],       bp);
        cp_async16(&Bs[s][(bkr + 8) * BSTR + bc], bp + (size_t)8 * Ncols);
        cp_commit();
    };

    issue(0, 0);

    for (int kt = 0; kt < KT; kt++) {
        cp_wait_all();
        __syncthreads();
        if (kt + 1 < KT) issue(kt + 1, (kt + 1) & 1);

        const float* Asb = As[kt & 1];
        const float* Bsb = Bs[kt & 1];

        #pragma unroll
        for (int ks = 0; ks < 2; ks++) {
            const int kb = ks * 8;

            uint32_t afr[2][4];
            #pragma unroll
            for (int mt = 0; mt < 2; mt++) {
                const int m0 = warpM * 32 + mt * 16 + grp;
                afr[mt][0] = __float_as_uint(Asb[(m0)     * ASTR + kb + tig]);
                afr[mt][1] = __float_as_uint(Asb[(m0 + 8) * ASTR + kb + tig]);
                afr[mt][2] = __float_as_uint(Asb[(m0)     * ASTR + kb + tig + 4]);
                afr[mt][3] = __float_as_uint(Asb[(m0 + 8) * ASTR + kb + tig + 4]);
            }
            uint32_t bfr[8][2];
            #pragma unroll
            for (int nt = 0; nt < 8; nt++) {
                const int n0 = warpN * 64 + nt * 8 + grp;
                bfr[nt][0] = __float_as_uint(Bsb[(kb + tig)     * BSTR + n0]);
                bfr[nt][1] = __float_as_uint(Bsb[(kb + tig + 4) * BSTR + n0]);
            }
            #pragma unroll
            for (int mt = 0; mt < 2; mt++)
                #pragma unroll
                for (int nt = 0; nt < 8; nt++)
                    mma_tf32(acc[mt][nt], afr[mt], bfr[nt]);
        }
        __syncthreads();
    }

    // ---------------- Epilogue ----------------
    #pragma unroll
    for (int mt = 0; mt < 2; mt++) {
        #pragma unroll
        for (int half = 0; half < 2; half++) {
            const int gr = rowBase + warpM * 32 + mt * 16 + grp + half * 8;
            const size_t crow = rowmapC ? (size_t)rowmapC[gr] : (size_t)gr;
            float* Cp = C + crow * (size_t)Ncols;
            const float* Rp = nullptr;
            if (EPI == 2) {
                const size_t rrow = rowmapRes ? (size_t)rowmapRes[gr] : (size_t)gr;
                Rp = Res + rrow * (size_t)Ncols;
            }
            #pragma unroll
            for (int nt = 0; nt < 8; nt++) {
                const int col = colBase + warpN * 64 + nt * 8 + 2 * tig;
                float v0 = acc[mt][nt][half * 2 + 0] + bias[col];
                float v1 = acc[mt][nt][half * 2 + 1] + bias[col + 1];
                if (EPI == 1) {
                    v0 = 0.5f * v0 * (1.0f + erff(v0 * 0.70710678118654752f));
                    v1 = 0.5f * v1 * (1.0f + erff(v1 * 0.70710678118654752f));
                    v0 = rtf32(v0); v1 = rtf32(v1);   // feeds fc2 tf32 A
                }
                if (EPI == 2) { v0 += Rp[col]; v1 += Rp[col + 1]; }
                *(float2*)(Cp + col) = make_float2(v0, v1);
            }
        }
    }
}

// ---------------------------------------------------------------------------
// Attention: one block per (window m, head h). 64 threads, one query row each.
// Output rounded to tf32 (feeds proj GEMM A operand).
// ---------------------------------------------------------------------------
__global__ __launch_bounds__(64)
void attn_kernel(const float* __restrict__ qkv, float* __restrict__ attn_out)
{
    const int m = blockIdx.x >> 3;
    const int h = blockIdx.x & 7;
    const int tid = threadIdx.x;

    __shared__ __align__(16) float Ks[W * DH];
    __shared__ __align__(16) float Vs[W * DH];

    const float* base = qkv + (size_t)m * W * QKVC + h * (3 * DH);

    for (int i = tid * 4; i < W * DH; i += 64 * 4) {
        const int row = i >> 5, col = i & 31;
        const float* rp = base + (size_t)row * QKVC;
        *(float4*)(Ks + i) = *(const float4*)(rp + DH + col);
        *(float4*)(Vs + i) = *(const float4*)(rp + 2 * DH + col);
    }
    __syncthreads();

    const int w = tid;
    const float* qp = base + (size_t)w * QKVC;
    float q[DH];
    #pragma unroll
    for (int d = 0; d < DH; d += 4)
        *(float4*)&q[d] = *(const float4*)(qp + d);

    const float scale = 0.17677669529663687f; // 1/sqrt(32)

    float S[W];
    #pragma unroll
    for (int j = 0; j < W; j++) {
        float s0 = 0.f, s1 = 0.f, s2 = 0.f, s3 = 0.f;
        #pragma unroll
        for (int d = 0; d < DH; d += 4) {
            float4 k4 = *(const float4*)&Ks[j * DH + d];
            s0 += q[d]     * k4.x;
            s1 += q[d + 1] * k4.y;
            s2 += q[d + 2] * k4.z;
            s3 += q[d + 3] * k4.w;
        }
        S[j] = (s0 + s1 + s2 + s3) * scale;
    }

    float mx = -1e30f;
    #pragma unroll
    for (int j = 0; j < W; j++) mx = fmaxf(mx, S[j]);
    float sum = 0.f;
    #pragma unroll
    for (int j = 0; j < W; j++) { S[j] = expf(S[j] - mx); sum += S[j]; }
    const float inv = 1.0f / sum;
    #pragma unroll
    for (int j = 0; j < W; j++) S[j] *= inv;

    float o[DH];
    #pragma unroll
    for (int d = 0; d < DH; d++) o[d] = 0.f;
    #pragma unroll
    for (int j = 0; j < W; j++) {
        const float p = S[j];
        #pragma unroll
        for (int d = 0; d < DH; d += 4) {
            float4 v4 = *(const float4*)&Vs[j * DH + d];
            o[d]     += p * v4.x;
            o[d + 1] += p * v4.y;
            o[d + 2] += p * v4.z;
            o[d + 3] += p * v4.w;
        }
    }

    float* op = attn_out + ((size_t)m * W + w) * DIM + h * DH;
    #pragma unroll
    for (int d = 0; d < DH; d += 4)
        *(float4*)(op + d) = make_float4(rtf32(o[d]), rtf32(o[d+1]),
                                         rtf32(o[d+2]), rtf32(o[d+3]));
}

// ---------------------------------------------------------------------------
// Launch
// ---------------------------------------------------------------------------
extern "C" void kernel_launch(void* const* d_in, const int* in_sizes, int n_in,
                              void* d_out, int out_size)
{
    int k = 0;
    const float* x      = (const float*)d_in[k++];
    const int*   index  = (const int*)  d_in[k++];
    if (n_in >= 15) k++;  // skip scalar M slot if present
    const float* n1g    = (const float*)d_in[k++];
    const float* n1b    = (const float*)d_in[k++];
    const float* qkv_w  = (const float*)d_in[k++];
    const float* qkv_b  = (const float*)d_in[k++];
    const float* proj_w = (const float*)d_in[k++];
    const float* proj_b = (const float*)d_in[k++];
    const float* n2g    = (const float*)d_in[k++];
    const float* n2b    = (const float*)d_in[k++];
    const float* fc1_w  = (const float*)d_in[k++];
    const float* fc1_b  = (const float*)d_in[k++];
    const float* fc2_w  = (const float*)d_in[k++];
    const float* fc2_b  = (const float*)d_in[k++];

    float* X = (float*)d_out;

    float *p_qkv, *p_attn, *p_h, *p_h2, *p_hid, *p_wr;
    int *p_rowmap;
    cudaGetSymbolAddress((void**)&p_qkv,    g_qkv);
    cudaGetSymbolAddress((void**)&p_attn,   g_attn);
    cudaGetSymbolAddress((void**)&p_h,      g_h);
    cudaGetSymbolAddress((void**)&p_h2,     g_h2);
    cudaGetSymbolAddress((void**)&p_hid,    g_hid);
    cudaGetSymbolAddress((void**)&p_wr,     g_wr);
    cudaGetSymbolAddress((void**)&p_rowmap, g_rowmap);

    // 0) tf32-round the weights into scratch (removes truncation bias in mma)
    round_copy_kernel<<<(DIM*QKVC)/1024, 256>>>(qkv_w,  p_wr + WOFF_QKV,  DIM*QKVC);
    round_copy_kernel<<<(DIM*DIM) /1024, 256>>>(proj_w, p_wr + WOFF_PROJ, DIM*DIM);
    round_copy_kernel<<<(DIM*HID) /1024, 256>>>(fc1_w,  p_wr + WOFF_FC1,  DIM*HID);
    round_copy_kernel<<<(HID*DIM) /1024, 256>>>(fc2_w,  p_wr + WOFF_FC2,  HID*DIM);

    // 1) LayerNorm1 over ALL rows -> X (d_out), tf32-rounded (feeds qkv A)
    ln_kernel<true><<<ROWS_ALL / 8, 256>>>(x, X, n1g, n1b, ROWS_ALL);

    // 2) Row map for active tokens
    rowmap_kernel<<<TOK / 256, 256>>>(index);

    // 3) QKV GEMM: gather(X) @ qkv_w + qkv_b -> g_qkv   [131072 x 768]
    gemm_tf32<0><<<dim3(QKVC / BN, TOK / BM), 256>>>(
        X, p_rowmap, p_wr + WOFF_QKV, qkv_b, p_qkv, nullptr, nullptr, nullptr, QKVC, DIM);

    // 4) Attention -> g_attn  [131072 x 256] (tf32-rounded output)
    attn_kernel<<<M_ACT * H, 64>>>(p_qkv, p_attn);

    // 5) Proj GEMM + shortcut (gathered X) -> g_h
    gemm_tf32<2><<<dim3(DIM / BN, TOK / BM), 256>>>(
        p_attn, nullptr, p_wr + WOFF_PROJ, proj_b, p_h, nullptr, X, p_rowmap, DIM, DIM);

    // 6) LayerNorm2: g_h -> g_h2, tf32-rounded (feeds fc1 A)
    ln_kernel<true><<<TOK / 8, 256>>>(p_h, p_h2, n2g, n2b, TOK);

    // 7) FC1 GEMM + GELU -> g_hid  [131072 x 1024] (output tf32-rounded)
    gemm_tf32<1><<<dim3(HID / BN, TOK / BM), 256>>>(
        p_h2, nullptr, p_wr + WOFF_FC1, fc1_b, p_hid, nullptr, nullptr, nullptr, HID, DIM);

    // 8) FC2 GEMM + residual(g_h), scatter rows into d_out (full fp32 epilogue)
    gemm_tf32<2><<<dim3(DIM / BN, TOK / BM), 256>>>(
        p_hid, nullptr, p_wr + WOFF_FC2, fc2_b, X, p_rowmap, p_h, nullptr, DIM, HID);

    (void)in_sizes; (void)out_size;
}

// round 12
// speedup vs baseline: 3.1482x; 1.3300x over previous
#include <cuda_runtime.h>
#include <cuda_fp16.h>
#include <math.h>
#include <stdint.h>

// ---------------------------------------------------------------------------
// Problem constants (fixed shapes)
// ---------------------------------------------------------------------------
#define NWIN   4096
#define W      64
#define DIM    256
#define H      8
#define DH     32
#define HID    1024
#define M_ACT  2048
#define TOK    (M_ACT * W)        // 131072 active tokens
#define ROWS_ALL (NWIN * W)       // 262144 total rows
#define QKVC   (3 * DIM)          // 768

// ---------------------------------------------------------------------------
// Scratch (device globals; allocation inside kernel_launch is forbidden)
// ---------------------------------------------------------------------------
__device__ __half g_xh  [(size_t)ROWS_ALL * DIM];  // LN1 out, half (GEMM A)
__device__ __half g_qkv [(size_t)TOK * QKVC];      // 201 MB
__device__ __half g_attn[(size_t)TOK * DIM];       // 67 MB
__device__ float  g_h   [(size_t)TOK * DIM];       // residual stream, fp32
__device__ __half g_h2  [(size_t)TOK * DIM];       // LN2 out, half
__device__ __half g_hid [(size_t)TOK * HID];       // 268 MB
__device__ int    g_rowmap[TOK];

// transposed + fp16-rounded weights, [N, K] K-major, concatenated
#define WOFF_QKV  0
#define WOFF_PROJ (DIM * QKVC)
#define WOFF_FC1  (WOFF_PROJ + DIM * DIM)
#define WOFF_FC2  (WOFF_FC1 + DIM * HID)
#define WTOTAL    (WOFF_FC2 + HID * DIM)
__device__ __half g_wh[WTOTAL];

// ---------------------------------------------------------------------------
// Weight transpose + fp16 round: dst[n*K + k] = (half)src[k*N + n]
// ---------------------------------------------------------------------------
__global__ void wtrans_kernel(const float* __restrict__ src,
                              __half* __restrict__ dst, int K, int N)
{
    int i = blockIdx.x * blockDim.x + threadIdx.x;
    if (i < K * N) {
        int n = i / K, k = i - n * K;
        dst[i] = __float2half_rn(src[(size_t)k * N + n]);
    }
}

// ---------------------------------------------------------------------------
// Row map
// ---------------------------------------------------------------------------
__global__ void rowmap_kernel(const int* __restrict__ index) {
    int t = blockIdx.x * blockDim.x + threadIdx.x;
    if (t < TOK) g_rowmap[t] = index[t >> 6] * W + (t & (W - 1));
}

// ---------------------------------------------------------------------------
// LayerNorm (one warp per row). Writes optional fp32 stream + half stream.
// ---------------------------------------------------------------------------
template<bool WRITE_F32>
__global__ __launch_bounds__(256)
void ln_kernel(const float* __restrict__ in, float* __restrict__ outf,
               __half* __restrict__ outh,
               const float* __restrict__ gam, const float* __restrict__ bet,
               int nrows)
{
    int warp = threadIdx.x >> 5;
    int lane = threadIdx.x & 31;
    int row  = blockIdx.x * 8 + warp;
    if (row >= nrows) return;

    const float* p = in + (size_t)row * DIM;
    float4 v0 = *(const float4*)(p + lane * 4);
    float4 v1 = *(const float4*)(p + 128 + lane * 4);

    float s = v0.x + v0.y + v0.z + v0.w + v1.x + v1.y + v1.z + v1.w;
    #pragma unroll
    for (int o = 16; o > 0; o >>= 1) s += __shfl_xor_sync(0xffffffffu, s, o);
    float mu = s * (1.0f / 256.0f);

    float d0 = v0.x - mu, d1 = v0.y - mu, d2 = v0.z - mu, d3 = v0.w - mu;
    float d4 = v1.x - mu, d5 = v1.y - mu, d6 = v1.z - mu, d7 = v1.w - mu;
    float vs = d0*d0 + d1*d1 + d2*d2 + d3*d3 + d4*d4 + d5*d5 + d6*d6 + d7*d7;
    #pragma unroll
    for (int o = 16; o > 0; o >>= 1) vs += __shfl_xor_sync(0xffffffffu, vs, o);
    float inv = rsqrtf(vs * (1.0f / 256.0f) + 1e-5f);

    float4 g0 = *(const float4*)(gam + lane * 4);
    float4 g1 = *(const float4*)(gam + 128 + lane * 4);
    float4 b0 = *(const float4*)(bet + lane * 4);
    float4 b1 = *(const float4*)(bet + 128 + lane * 4);

    float4 o0, o1;
    o0.x = d0 * inv * g0.x + b0.x;  o0.y = d1 * inv * g0.y + b0.y;
    o0.z = d2 * inv * g0.z + b0.z;  o0.w = d3 * inv * g0.w + b0.w;
    o1.x = d4 * inv * g1.x + b1.x;  o1.y = d5 * inv * g1.y + b1.y;
    o1.z = d6 * inv * g1.z + b1.z;  o1.w = d7 * inv * g1.w + b1.w;

    if (WRITE_F32) {
        float* q = outf + (size_t)row * DIM;
        *(float4*)(q + lane * 4) = o0;
        *(float4*)(q + 128 + lane * 4) = o1;
    }
    __half* qh = outh + (size_t)row * DIM;
    half2 h0 = __floats2half2_rn(o0.x, o0.y);
    half2 h1 = __floats2half2_rn(o0.z, o0.w);
    half2 h2 = __floats2half2_rn(o1.x, o1.y);
    half2 h3 = __floats2half2_rn(o1.z, o1.w);
    *(half2*)(qh + lane * 4)       = h0;
    *(half2*)(qh + lane * 4 + 2)   = h1;
    *(half2*)(qh + 128 + lane * 4)     = h2;
    *(half2*)(qh + 128 + lane * 4 + 2) = h3;
}

// ---------------------------------------------------------------------------
// fp16 tensor-core GEMM (mma.sync m16n8k16, f32 accum):
//   C[M,N] = A[M,K] @ Bt[N,K]^T + bias
//   EPI 0: bias | 1: bias+GELU | 2: bias+residual(fp32)
//   OUTH: write half | else fp32
// CTA tile 128x128, BK=32 halves, 3-stage cp.async pipeline, 256 threads,
// 8 warps (4x2), warp tile 32x64.
// ---------------------------------------------------------------------------
#define NSTG 3
#define BKH 32
#define ASTRH 40                      // halves per smem row (pad: 80 bytes)
#define STAGEB (128 * ASTRH * 2)      // 10240 bytes per matrix per stage
#define SMEM_H (2 * NSTG * STAGEB)    // 61440 bytes

__device__ __forceinline__ void cp_async16s(uint32_t smem, const void* gmem) {
    asm volatile("cp.async.cg.shared.global [%0], [%1], 16;\n" :: "r"(smem), "l"(gmem));
}
__device__ __forceinline__ void cp_commit() { asm volatile("cp.async.commit_group;\n"); }
template<int N> __device__ __forceinline__ void cp_wait() {
    asm volatile("cp.async.wait_group %0;\n" :: "n"(N));
}

__device__ __forceinline__ void mma_f16(float* c, const uint32_t* a, const uint32_t* b) {
    asm volatile(
        "mma.sync.aligned.m16n8k16.row.col.f32.f16.f16.f32 "
        "{%0,%1,%2,%3},{%4,%5,%6,%7},{%8,%9},{%0,%1,%2,%3};\n"
        : "+f"(c[0]), "+f"(c[1]), "+f"(c[2]), "+f"(c[3])
        : "r"(a[0]), "r"(a[1]), "r"(a[2]), "r"(a[3]), "r"(b[0]), "r"(b[1]));
}

template<int EPI, bool OUTH>
__global__ __launch_bounds__(256)
void gemm_h(const __half* __restrict__ A, const int* __restrict__ rowmapA,
            const __half* __restrict__ Bt, const float* __restrict__ bias,
            void* __restrict__ Cv, const int* __restrict__ rowmapC,
            const float* __restrict__ Res, const int* __restrict__ rowmapRes,
            int Ncols, int K)
{
    extern __shared__ __align__(16) char dyn[];
    const uint32_t sbase = (uint32_t)__cvta_generic_to_shared(dyn);

    const int tid = threadIdx.x;
    const int rowBase = blockIdx.y * 128;
    const int colBase = blockIdx.x * 128;

    // loaders: thread -> row r = tid>>1, chunks c0, c0+1 (16B each)
    const int r  = tid >> 1;
    const int c0 = (tid & 1) * 2;
    const int gra = rowBase + r;
    const size_t arow = rowmapA ? (size_t)rowmapA[gra] : (size_t)gra;
    const __half* Ag = A + arow * (size_t)K;
    const __half* Bg = Bt + (size_t)(colBase + r) * K;
    const uint32_t sArow = (uint32_t)(r * (ASTRH * 2));

    const int warp  = tid >> 5;
    const int lane  = tid & 31;
    const int warpM = warp >> 1;     // 0..3
    const int warpN = warp & 1;      // 0..1
    const int grp   = lane >> 2;
    const int tig   = lane & 3;

    float acc[2][8][4];
    #pragma unroll
    for (int mt = 0; mt < 2; mt++)
        #pragma unroll
        for (int nt = 0; nt < 8; nt++)
            #pragma unroll
            for (int j = 0; j < 4; j++) acc[mt][nt][j] = 0.0f;

    const int KT = K / BKH;

    auto issue = [&](int kt) {
        const int s = kt % NSTG;
        const uint32_t aB = sbase + s * STAGEB;
        const uint32_t bB = sbase + NSTG * STAGEB + s * STAGEB;
        const __half* ag = Ag + kt * BKH;
        const __half* bg = Bg + kt * BKH;
        cp_async16s(aB + sArow + c0 * 16,       ag + c0 * 8);
        cp_async16s(aB + sArow + (c0 + 1) * 16, ag + (c0 + 1) * 8);
        cp_async16s(bB + sArow + c0 * 16,       bg + c0 * 8);
        cp_async16s(bB + sArow + (c0 + 1) * 16, bg + (c0 + 1) * 8);
        cp_commit();
    };

    issue(0);
    issue(1);

    for (int kt = 0; kt < KT; kt++) {
        if (kt < KT - 1) cp_wait<1>(); else cp_wait<0>();
        __syncthreads();
        if (kt + 2 < KT) issue(kt + 2);

        const int s = kt % NSTG;
        const __half* Asb = (const __half*)(dyn + s * STAGEB);
        const __half* Bsb = (const __half*)(dyn + NSTG * STAGEB + s * STAGEB);

        #pragma unroll
        for (int ks = 0; ks < 2; ks++) {
            const int kb = ks * 16;

            uint32_t afr[2][4];
            #pragma unroll
            for (int mt = 0; mt < 2; mt++) {
                const int m0 = warpM * 32 + mt * 16 + grp;
                afr[mt][0] = *(const uint32_t*)&Asb[(m0)     * ASTRH + kb + 2 * tig];
                afr[mt][1] = *(const uint32_t*)&Asb[(m0 + 8) * ASTRH + kb + 2 * tig];
                afr[mt][2] = *(const uint32_t*)&Asb[(m0)     * ASTRH + kb + 2 * tig + 8];
                afr[mt][3] = *(const uint32_t*)&Asb[(m0 + 8) * ASTRH + kb + 2 * tig + 8];
            }
            uint32_t bfr[8][2];
            #pragma unroll
            for (int nt = 0; nt < 8; nt++) {
                const int n0 = warpN * 64 + nt * 8 + grp;
                bfr[nt][0] = *(const uint32_t*)&Bsb[n0 * ASTRH + kb + 2 * tig];
                bfr[nt][1] = *(const uint32_t*)&Bsb[n0 * ASTRH + kb + 2 * tig + 8];
            }
            #pragma unroll
            for (int mt = 0; mt < 2; mt++)
                #pragma unroll
                for (int nt = 0; nt < 8; nt++)
                    mma_f16(acc[mt][nt], afr[mt], bfr[nt]);
        }
        __syncthreads();
    }

    // ---------------- Epilogue ----------------
    #pragma unroll
    for (int mt = 0; mt < 2; mt++) {
        #pragma unroll
        for (int hf = 0; hf < 2; hf++) {
            const int gr = rowBase + warpM * 32 + mt * 16 + grp + hf * 8;
            const size_t crow = rowmapC ? (size_t)rowmapC[gr] : (size_t)gr;
            const float* Rp = nullptr;
            if (EPI == 2) {
                const size_t rrow = rowmapRes ? (size_t)rowmapRes[gr] : (size_t)gr;
                Rp = Res + rrow * (size_t)Ncols;
            }
            #pragma unroll
            for (int nt = 0; nt < 8; nt++) {
                const int col = colBase + warpN * 64 + nt * 8 + 2 * tig;
                float v0 = acc[mt][nt][hf * 2 + 0] + __ldg(bias + col);
                float v1 = acc[mt][nt][hf * 2 + 1] + __ldg(bias + col + 1);
                if (EPI == 1) {
                    v0 = 0.5f * v0 * (1.0f + erff(v0 * 0.70710678118654752f));
                    v1 = 0.5f * v1 * (1.0f + erff(v1 * 0.70710678118654752f));
                }
                if (EPI == 2) { v0 += Rp[col]; v1 += Rp[col + 1]; }
                if (OUTH) {
                    __half* Cp = (__half*)Cv + crow * (size_t)Ncols;
                    *(half2*)(Cp + col) = __floats2half2_rn(v0, v1);
                } else {
                    float* Cp = (float*)Cv + crow * (size_t)Ncols;
                    *(float2*)(Cp + col) = make_float2(v0, v1);
                }
            }
        }
    }
}

// ---------------------------------------------------------------------------
// Attention: one block per (window m, head h). 64 threads, one query row each.
// Half qkv input (converted to fp32 in staging); half output.
// ---------------------------------------------------------------------------
__global__ __launch_bounds__(64)
void attn_kernel(const __half* __restrict__ qkv, __half* __restrict__ attn_out)
{
    const int m = blockIdx.x >> 3;
    const int h = blockIdx.x & 7;
    const int tid = threadIdx.x;

    __shared__ __align__(16) float Ks[W * DH];
    __shared__ __align__(16) float Vs[W * DH];

    const __half* base = qkv + (size_t)m * W * QKVC + h * (3 * DH);

    for (int i = tid * 4; i < W * DH; i += 64 * 4) {
        const int row = i >> 5, col = i & 31;
        const __half* rp = base + (size_t)row * QKVC;
        half2 k01 = *(const half2*)(rp + DH + col);
        half2 k23 = *(const half2*)(rp + DH + col + 2);
        half2 v01 = *(const half2*)(rp + 2 * DH + col);
        half2 v23 = *(const half2*)(rp + 2 * DH + col + 2);
        float2 kf0 = __half22float2(k01), kf1 = __half22float2(k23);
        float2 vf0 = __half22float2(v01), vf1 = __half22float2(v23);
        *(float4*)(Ks + i) = make_float4(kf0.x, kf0.y, kf1.x, kf1.y);
        *(float4*)(Vs + i) = make_float4(vf0.x, vf0.y, vf1.x, vf1.y);
    }
    __syncthreads();

    const int w = tid;
    const __half* qp = base + (size_t)w * QKVC;
    float q[DH];
    #pragma unroll
    for (int d = 0; d < DH; d += 2) {
        float2 f = __half22float2(*(const half2*)(qp + d));
        q[d] = f.x; q[d + 1] = f.y;
    }

    const float scale = 0.17677669529663687f;

    float S[W];
    #pragma unroll
    for (int j = 0; j < W; j++) {
        float s0 = 0.f, s1 = 0.f, s2 = 0.f, s3 = 0.f;
        #pragma unroll
        for (int d = 0; d < DH; d += 4) {
            float4 k4 = *(const float4*)&Ks[j * DH + d];
            s0 += q[d]     * k4.x;
            s1 += q[d + 1] * k4.y;
            s2 += q[d + 2] * k4.z;
            s3 += q[d + 3] * k4.w;
        }
        S[j] = (s0 + s1 + s2 + s3) * scale;
    }

    float mx = -1e30f;
    #pragma unroll
    for (int j = 0; j < W; j++) mx = fmaxf(mx, S[j]);
    float sum = 0.f;
    #pragma unroll
    for (int j = 0; j < W; j++) { S[j] = expf(S[j] - mx); sum += S[j]; }
    const float inv = 1.0f / sum;
    #pragma unroll
    for (int j = 0; j < W; j++) S[j] *= inv;

    float o[DH];
    #pragma unroll
    for (int d = 0; d < DH; d++) o[d] = 0.f;
    #pragma unroll
    for (int j = 0; j < W; j++) {
        const float p = S[j];
        #pragma unroll
        for (int d = 0; d < DH; d += 4) {
            float4 v4 = *(const float4*)&Vs[j * DH + d];
            o[d]     += p * v4.x;
            o[d + 1] += p * v4.y;
            o[d + 2] += p * v4.z;
            o[d + 3] += p * v4.w;
        }
    }

    __half* op = attn_out + ((size_t)m * W + w) * DIM + h * DH;
    #pragma unroll
    for (int d = 0; d < DH; d += 2)
        *(half2*)(op + d) = __floats2half2_rn(o[d], o[d + 1]);
}

// ---------------------------------------------------------------------------
// Launch
// ---------------------------------------------------------------------------
extern "C" void kernel_launch(void* const* d_in, const int* in_sizes, int n_in,
                              void* d_out, int out_size)
{
    int k = 0;
    const float* x      = (const float*)d_in[k++];
    const int*   index  = (const int*)  d_in[k++];
    if (n_in >= 15) k++;  // skip scalar M slot if present
    const float* n1g    = (const float*)d_in[k++];
    const float* n1b    = (const float*)d_in[k++];
    const float* qkv_w  = (const float*)d_in[k++];
    const float* qkv_b  = (const float*)d_in[k++];
    const float* proj_w = (const float*)d_in[k++];
    const float* proj_b = (const float*)d_in[k++];
    const float* n2g    = (const float*)d_in[k++];
    const float* n2b    = (const float*)d_in[k++];
    const float* fc1_w  = (const float*)d_in[k++];
    const float* fc1_b  = (const float*)d_in[k++];
    const float* fc2_w  = (const float*)d_in[k++];
    const float* fc2_b  = (const float*)d_in[k++];

    float* X = (float*)d_out;

    __half *p_xh, *p_qkv, *p_attn, *p_h2, *p_hid, *p_wh;
    float *p_h;
    int *p_rowmap;
    cudaGetSymbolAddress((void**)&p_xh,     g_xh);
    cudaGetSymbolAddress((void**)&p_qkv,    g_qkv);
    cudaGetSymbolAddress((void**)&p_attn,   g_attn);
    cudaGetSymbolAddress((void**)&p_h,      g_h);
    cudaGetSymbolAddress((void**)&p_h2,     g_h2);
    cudaGetSymbolAddress((void**)&p_hid,    g_hid);
    cudaGetSymbolAddress((void**)&p_wh,     g_wh);
    cudaGetSymbolAddress((void**)&p_rowmap, g_rowmap);

    cudaFuncSetAttribute(gemm_h<0, true>,  cudaFuncAttributeMaxDynamicSharedMemorySize, SMEM_H);
    cudaFuncSetAttribute(gemm_h<1, true>,  cudaFuncAttributeMaxDynamicSharedMemorySize, SMEM_H);
    cudaFuncSetAttribute(gemm_h<2, false>, cudaFuncAttributeMaxDynamicSharedMemorySize, SMEM_H);

    // 0) transpose + fp16-round weights -> [N,K] K-major
    wtrans_kernel<<<(DIM*QKVC + 255)/256, 256>>>(qkv_w,  p_wh + WOFF_QKV,  DIM, QKVC);
    wtrans_kernel<<<(DIM*DIM  + 255)/256, 256>>>(proj_w, p_wh + WOFF_PROJ, DIM, DIM);
    wtrans_kernel<<<(DIM*HID  + 255)/256, 256>>>(fc1_w,  p_wh + WOFF_FC1,  DIM, HID);
    wtrans_kernel<<<(HID*DIM  + 255)/256, 256>>>(fc2_w,  p_wh + WOFF_FC2,  HID, DIM);

    // 1) LayerNorm1: exact fp32 -> d_out, half copy -> g_xh
    ln_kernel<true><<<ROWS_ALL / 8, 256>>>(x, X, p_xh, n1g, n1b, ROWS_ALL);

    // 2) Row map
    rowmap_kernel<<<TOK / 256, 256>>>(index);

    // 3) QKV: gather(g_xh) @ qkv_w + b -> g_qkv (half)  [131072 x 768]
    gemm_h<0, true><<<dim3(QKVC/128, TOK/128), 256, SMEM_H>>>(
        p_xh, p_rowmap, p_wh + WOFF_QKV, qkv_b, p_qkv, nullptr, nullptr, nullptr, QKVC, DIM);

    // 4) Attention -> g_attn (half)
    attn_kernel<<<M_ACT * H, 64>>>(p_qkv, p_attn);

    // 5) Proj + shortcut(gathered fp32 X) -> g_h (fp32)
    gemm_h<2, false><<<dim3(DIM/128, TOK/128), 256, SMEM_H>>>(
        p_attn, nullptr, p_wh + WOFF_PROJ, proj_b, p_h, nullptr, X, p_rowmap, DIM, DIM);

    // 6) LayerNorm2: g_h -> g_h2 (half only)
    ln_kernel<false><<<TOK / 8, 256>>>(p_h, nullptr, p_h2, n2g, n2b, TOK);

    // 7) FC1 + GELU -> g_hid (half)  [131072 x 1024]
    gemm_h<1, true><<<dim3(HID/128, TOK/128), 256, SMEM_H>>>(
        p_h2, nullptr, p_wh + WOFF_FC1, fc1_b, p_hid, nullptr, nullptr, nullptr, HID, DIM);

    // 8) FC2 + residual(g_h fp32), scatter fp32 rows into d_out
    gemm_h<2, false><<<dim3(DIM/128, TOK/128), 256, SMEM_H>>>(
        p_hid, nullptr, p_wh + WOFF_FC2, fc2_b, X, p_rowmap, p_h, nullptr, DIM, HID);

    (void)in_sizes; (void)out_size;
}

// round 13
// speedup vs baseline: 3.1613x; 1.0042x over previous
#include <cuda_runtime.h>
#include <cuda_fp16.h>
#include <math.h>
#include <stdint.h>

// ---------------------------------------------------------------------------
// Problem constants (fixed shapes)
// ---------------------------------------------------------------------------
#define NWIN   4096
#define W      64
#define DIM    256
#define H      8
#define DH     32
#define HID    1024
#define M_ACT  2048
#define TOK    (M_ACT * W)        // 131072 active tokens
#define ROWS_ALL (NWIN * W)       // 262144 total rows
#define QKVC   (3 * DIM)          // 768

// ---------------------------------------------------------------------------
// Scratch (device globals; allocation inside kernel_launch is forbidden)
// ---------------------------------------------------------------------------
__device__ __half g_xh  [(size_t)ROWS_ALL * DIM];  // LN1 out, half (GEMM A)
__device__ __half g_qkv [(size_t)TOK * QKVC];
__device__ __half g_attn[(size_t)TOK * DIM];
__device__ float  g_h   [(size_t)TOK * DIM];       // residual stream, fp32
__device__ __half g_h2  [(size_t)TOK * DIM];
__device__ __half g_hid [(size_t)TOK * HID];
__device__ int    g_rowmap[TOK];

// transposed + fp16-rounded weights, [N, K] K-major, concatenated
#define WOFF_QKV  0
#define WOFF_PROJ (DIM * QKVC)
#define WOFF_FC1  (WOFF_PROJ + DIM * DIM)
#define WOFF_FC2  (WOFF_FC1 + DIM * HID)
#define WTOTAL    (WOFF_FC2 + HID * DIM)
__device__ __half g_wh[WTOTAL];

// ---------------------------------------------------------------------------
// Weight transpose + fp16 round: dst[n*K + k] = (half)src[k*N + n]
// ---------------------------------------------------------------------------
__global__ void wtrans_kernel(const float* __restrict__ src,
                              __half* __restrict__ dst, int K, int N)
{
    int i = blockIdx.x * blockDim.x + threadIdx.x;
    if (i < K * N) {
        int n = i / K, k = i - n * K;
        dst[i] = __float2half_rn(src[(size_t)k * N + n]);
    }
}

// ---------------------------------------------------------------------------
// Row map
// ---------------------------------------------------------------------------
__global__ void rowmap_kernel(const int* __restrict__ index) {
    int t = blockIdx.x * blockDim.x + threadIdx.x;
    if (t < TOK) g_rowmap[t] = index[t >> 6] * W + (t & (W - 1));
}

// ---------------------------------------------------------------------------
// LayerNorm (one warp per row). Writes optional fp32 stream + half stream.
// ---------------------------------------------------------------------------
template<bool WRITE_F32>
__global__ __launch_bounds__(256)
void ln_kernel(const float* __restrict__ in, float* __restrict__ outf,
               __half* __restrict__ outh,
               const float* __restrict__ gam, const float* __restrict__ bet,
               int nrows)
{
    int warp = threadIdx.x >> 5;
    int lane = threadIdx.x & 31;
    int row  = blockIdx.x * 8 + warp;
    if (row >= nrows) return;

    const float* p = in + (size_t)row * DIM;
    float4 v0 = *(const float4*)(p + lane * 4);
    float4 v1 = *(const float4*)(p + 128 + lane * 4);

    float s = v0.x + v0.y + v0.z + v0.w + v1.x + v1.y + v1.z + v1.w;
    #pragma unroll
    for (int o = 16; o > 0; o >>= 1) s += __shfl_xor_sync(0xffffffffu, s, o);
    float mu = s * (1.0f / 256.0f);

    float d0 = v0.x - mu, d1 = v0.y - mu, d2 = v0.z - mu, d3 = v0.w - mu;
    float d4 = v1.x - mu, d5 = v1.y - mu, d6 = v1.z - mu, d7 = v1.w - mu;
    float vs = d0*d0 + d1*d1 + d2*d2 + d3*d3 + d4*d4 + d5*d5 + d6*d6 + d7*d7;
    #pragma unroll
    for (int o = 16; o > 0; o >>= 1) vs += __shfl_xor_sync(0xffffffffu, vs, o);
    float inv = rsqrtf(vs * (1.0f / 256.0f) + 1e-5f);

    float4 g0 = *(const float4*)(gam + lane * 4);
    float4 g1 = *(const float4*)(gam + 128 + lane * 4);
    float4 b0 = *(const float4*)(bet + lane * 4);
    float4 b1 = *(const float4*)(bet + 128 + lane * 4);

    float4 o0, o1;
    o0.x = d0 * inv * g0.x + b0.x;  o0.y = d1 * inv * g0.y + b0.y;
    o0.z = d2 * inv * g0.z + b0.z;  o0.w = d3 * inv * g0.w + b0.w;
    o1.x = d4 * inv * g1.x + b1.x;  o1.y = d5 * inv * g1.y + b1.y;
    o1.z = d6 * inv * g1.z + b1.z;  o1.w = d7 * inv * g1.w + b1.w;

    if (WRITE_F32) {
        float* q = outf + (size_t)row * DIM;
        *(float4*)(q + lane * 4) = o0;
        *(float4*)(q + 128 + lane * 4) = o1;
    }
    __half* qh = outh + (size_t)row * DIM;
    *(half2*)(qh + lane * 4)           = __floats2half2_rn(o0.x, o0.y);
    *(half2*)(qh + lane * 4 + 2)       = __floats2half2_rn(o0.z, o0.w);
    *(half2*)(qh + 128 + lane * 4)     = __floats2half2_rn(o1.x, o1.y);
    *(half2*)(qh + 128 + lane * 4 + 2) = __floats2half2_rn(o1.z, o1.w);
}

// ---------------------------------------------------------------------------
// fp16 tensor-core GEMM (mma.sync m16n8k16, f32 accum):
//   C[M,N] = A[M,K] @ Bt[N,K]^T + bias
//   EPI 0: bias | 1: bias+GELU | 2: bias+residual(fp32)
//   OUTH: write half | else fp32
// CTA tile 128x128, BK=32 halves, 4-stage cp.async pipeline (wait_group 2),
// 256 threads, 8 warps (4x2), warp tile 32x64, ldmatrix fragment loads.
// ---------------------------------------------------------------------------
#define NSTG 4
#define BKH 32
#define ASTRH 40                      // halves per smem row (pad: 80 bytes, conflict-free)
#define STAGEB (128 * ASTRH * 2)      // 10240 bytes per matrix per stage
#define SMEM_H (2 * NSTG * STAGEB)    // 81920 bytes

__device__ __forceinline__ void cp_async16s(uint32_t smem, const void* gmem) {
    asm volatile("cp.async.cg.shared.global [%0], [%1], 16;\n" :: "r"(smem), "l"(gmem));
}
__device__ __forceinline__ void cp_commit() { asm volatile("cp.async.commit_group;\n"); }
template<int N> __device__ __forceinline__ void cp_wait() {
    asm volatile("cp.async.wait_group %0;\n" :: "n"(N));
}

__device__ __forceinline__ void ldmx4(uint32_t* r, uint32_t addr) {
    asm volatile("ldmatrix.sync.aligned.m8n8.x4.shared.b16 {%0,%1,%2,%3}, [%4];"
                 : "=r"(r[0]), "=r"(r[1]), "=r"(r[2]), "=r"(r[3]) : "r"(addr));
}

__device__ __forceinline__ void mma_f16(float* c, const uint32_t* a, const uint32_t* b) {
    asm volatile(
        "mma.sync.aligned.m16n8k16.row.col.f32.f16.f16.f32 "
        "{%0,%1,%2,%3},{%4,%5,%6,%7},{%8,%9},{%0,%1,%2,%3};\n"
        : "+f"(c[0]), "+f"(c[1]), "+f"(c[2]), "+f"(c[3])
        : "r"(a[0]), "r"(a[1]), "r"(a[2]), "r"(a[3]), "r"(b[0]), "r"(b[1]));
}

template<int EPI, bool OUTH>
__global__ __launch_bounds__(256)
void gemm_h(const __half* __restrict__ A, const int* __restrict__ rowmapA,
            const __half* __restrict__ Bt, const float* __restrict__ bias,
            void* __restrict__ Cv, const int* __restrict__ rowmapC,
            const float* __restrict__ Res, const int* __restrict__ rowmapRes,
            int Ncols, int K)
{
    extern __shared__ __align__(16) char dyn[];
    const uint32_t sbase = (uint32_t)__cvta_generic_to_shared(dyn);

    const int tid = threadIdx.x;
    const int rowBase = blockIdx.y * 128;
    const int colBase = blockIdx.x * 128;

    // loaders: thread -> row r = tid>>1, chunks c0, c0+1 (16B each)
    const int r  = tid >> 1;
    const int c0 = (tid & 1) * 2;
    const int gra = rowBase + r;
    const size_t arow = rowmapA ? (size_t)rowmapA[gra] : (size_t)gra;
    const __half* Ag = A + arow * (size_t)K;
    const __half* Bg = Bt + (size_t)(colBase + r) * K;
    const uint32_t sArow = (uint32_t)(r * (ASTRH * 2));

    const int warp  = tid >> 5;
    const int lane  = tid & 31;
    const int warpM = warp >> 1;     // 0..3
    const int warpN = warp & 1;      // 0..1
    const int grp   = lane >> 2;
    const int tig   = lane & 3;

    float acc[2][8][4];
    #pragma unroll
    for (int mt = 0; mt < 2; mt++)
        #pragma unroll
        for (int nt = 0; nt < 8; nt++)
            #pragma unroll
            for (int j = 0; j < 4; j++) acc[mt][nt][j] = 0.0f;

    const int KT = K / BKH;

    auto issue = [&](int kt) {
        const int s = kt % NSTG;
        const uint32_t aB = sbase + s * STAGEB;
        const uint32_t bB = sbase + NSTG * STAGEB + s * STAGEB;
        const __half* ag = Ag + kt * BKH;
        const __half* bg = Bg + kt * BKH;
        cp_async16s(aB + sArow + c0 * 16,       ag + c0 * 8);
        cp_async16s(aB + sArow + (c0 + 1) * 16, ag + (c0 + 1) * 8);
        cp_async16s(bB + sArow + c0 * 16,       bg + c0 * 8);
        cp_async16s(bB + sArow + (c0 + 1) * 16, bg + (c0 + 1) * 8);
        cp_commit();
    };

    issue(0);
    if (KT > 1) issue(1);
    if (KT > 2) issue(2);

    // ldmatrix address precompute (byte offsets within a stage)
    // A tiles: row = m0 + (lane&15), colHalf = kb + (lane>>4)*8
    const uint32_t aLdRow = (uint32_t)(warpM * 32 + (lane & 15));
    const uint32_t aLdCol = (uint32_t)((lane >> 4) * 8);
    // B tiles: row = n0 + (lane&7) + (lane>>4)*8, colHalf = kb + ((lane>>3)&1)*8
    const uint32_t bLdRow0 = (uint32_t)(warpN * 64 + (lane & 7) + (lane >> 4) * 8);
    const uint32_t bLdCol = (uint32_t)(((lane >> 3) & 1) * 8);

    for (int kt = 0; kt < KT; kt++) {
        const int rem = KT - 1 - kt;
        if (rem >= 2)      cp_wait<2>();
        else if (rem == 1) cp_wait<1>();
        else               cp_wait<0>();
        __syncthreads();
        if (kt + 3 < KT) issue(kt + 3);

        const int s = kt % NSTG;
        const uint32_t aB = sbase + s * STAGEB;
        const uint32_t bB = sbase + NSTG * STAGEB + s * STAGEB;

        #pragma unroll
        for (int ks = 0; ks < 2; ks++) {
            const uint32_t kb = (uint32_t)(ks * 16);

            uint32_t afr[2][4];
            #pragma unroll
            for (int mt = 0; mt < 2; mt++) {
                uint32_t addr = aB + ((aLdRow + mt * 16) * ASTRH + kb + aLdCol) * 2;
                ldmx4(afr[mt], addr);
            }
            uint32_t bfr[8][2];
            #pragma unroll
            for (int np = 0; np < 4; np++) {
                uint32_t t[4];
                uint32_t addr = bB + ((bLdRow0 + np * 16) * ASTRH + kb + bLdCol) * 2;
                ldmx4(t, addr);
                bfr[2 * np][0]     = t[0];
                bfr[2 * np][1]     = t[1];
                bfr[2 * np + 1][0] = t[2];
                bfr[2 * np + 1][1] = t[3];
            }
            #pragma unroll
            for (int mt = 0; mt < 2; mt++)
                #pragma unroll
                for (int nt = 0; nt < 8; nt++)
                    mma_f16(acc[mt][nt], afr[mt], bfr[nt]);
        }
        __syncthreads();
    }

    // ---------------- Epilogue ----------------
    #pragma unroll
    for (int mt = 0; mt < 2; mt++) {
        #pragma unroll
        for (int hf = 0; hf < 2; hf++) {
            const int gr = rowBase + warpM * 32 + mt * 16 + grp + hf * 8;
            const size_t crow = rowmapC ? (size_t)rowmapC[gr] : (size_t)gr;
            const float* Rp = nullptr;
            if (EPI == 2) {
                const size_t rrow = rowmapRes ? (size_t)rowmapRes[gr] : (size_t)gr;
                Rp = Res + rrow * (size_t)Ncols;
            }
            #pragma unroll
            for (int nt = 0; nt < 8; nt++) {
                const int col = colBase + warpN * 64 + nt * 8 + 2 * tig;
                float v0 = acc[mt][nt][hf * 2 + 0] + __ldg(bias + col);
                float v1 = acc[mt][nt][hf * 2 + 1] + __ldg(bias + col + 1);
                if (EPI == 1) {
                    v0 = 0.5f * v0 * (1.0f + erff(v0 * 0.70710678118654752f));
                    v1 = 0.5f * v1 * (1.0f + erff(v1 * 0.70710678118654752f));
                }
                if (EPI == 2) { v0 += Rp[col]; v1 += Rp[col + 1]; }
                if (OUTH) {
                    __half* Cp = (__half*)Cv + crow * (size_t)Ncols;
                    *(half2*)(Cp + col) = __floats2half2_rn(v0, v1);
                } else {
                    float* Cp = (float*)Cv + crow * (size_t)Ncols;
                    *(float2*)(Cp + col) = make_float2(v0, v1);
                }
            }
        }
    }
}

// ---------------------------------------------------------------------------
// Attention: one block per (window m, head h). 64 threads, one query row each.
// ---------------------------------------------------------------------------
__global__ __launch_bounds__(64)
void attn_kernel(const __half* __restrict__ qkv, __half* __restrict__ attn_out)
{
    const int m = blockIdx.x >> 3;
    const int h = blockIdx.x & 7;
    const int tid = threadIdx.x;

    __shared__ __align__(16) float Ks[W * DH];
    __shared__ __align__(16) float Vs[W * DH];

    const __half* base = qkv + (size_t)m * W * QKVC + h * (3 * DH);

    for (int i = tid * 4; i < W * DH; i += 64 * 4) {
        const int row = i >> 5, col = i & 31;
        const __half* rp = base + (size_t)row * QKVC;
        half2 k01 = *(const half2*)(rp + DH + col);
        half2 k23 = *(const half2*)(rp + DH + col + 2);
        half2 v01 = *(const half2*)(rp + 2 * DH + col);
        half2 v23 = *(const half2*)(rp + 2 * DH + col + 2);
        float2 kf0 = __half22float2(k01), kf1 = __half22float2(k23);
        float2 vf0 = __half22float2(v01), vf1 = __half22float2(v23);
        *(float4*)(Ks + i) = make_float4(kf0.x, kf0.y, kf1.x, kf1.y);
        *(float4*)(Vs + i) = make_float4(vf0.x, vf0.y, vf1.x, vf1.y);
    }
    __syncthreads();

    const int w = tid;
    const __half* qp = base + (size_t)w * QKVC;
    float q[DH];
    #pragma unroll
    for (int d = 0; d < DH; d += 2) {
        float2 f = __half22float2(*(const half2*)(qp + d));
        q[d] = f.x; q[d + 1] = f.y;
    }

    const float scale = 0.17677669529663687f;

    float S[W];
    #pragma unroll
    for (int j = 0; j < W; j++) {
        float s0 = 0.f, s1 = 0.f, s2 = 0.f, s3 = 0.f;
        #pragma unroll
        for (int d = 0; d < DH; d += 4) {
            float4 k4 = *(const float4*)&Ks[j * DH + d];
            s0 += q[d]     * k4.x;
            s1 += q[d + 1] * k4.y;
            s2 += q[d + 2] * k4.z;
            s3 += q[d + 3] * k4.w;
        }
        S[j] = (s0 + s1 + s2 + s3) * scale;
    }

    float mx = -1e30f;
    #pragma unroll
    for (int j = 0; j < W; j++) mx = fmaxf(mx, S[j]);
    float sum = 0.f;
    #pragma unroll
    for (int j = 0; j < W; j++) { S[j] = expf(S[j] - mx); sum += S[j]; }
    const float inv = 1.0f / sum;
    #pragma unroll
    for (int j = 0; j < W; j++) S[j] *= inv;

    float o[DH];
    #pragma unroll
    for (int d = 0; d < DH; d++) o[d] = 0.f;
    #pragma unroll
    for (int j = 0; j < W; j++) {
        const float p = S[j];
        #pragma unroll
        for (int d = 0; d < DH; d += 4) {
            float4 v4 = *(const float4*)&Vs[j * DH + d];
            o[d]     += p * v4.x;
            o[d + 1] += p * v4.y;
            o[d + 2] += p * v4.z;
            o[d + 3] += p * v4.w;
        }
    }

    __half* op = attn_out + ((size_t)m * W + w) * DIM + h * DH;
    #pragma unroll
    for (int d = 0; d < DH; d += 2)
        *(half2*)(op + d) = __floats2half2_rn(o[d], o[d + 1]);
}

// ---------------------------------------------------------------------------
// Launch
// ---------------------------------------------------------------------------
extern "C" void kernel_launch(void* const* d_in, const int* in_sizes, int n_in,
                              void* d_out, int out_size)
{
    int k = 0;
    const float* x      = (const float*)d_in[k++];
    const int*   index  = (const int*)  d_in[k++];
    if (n_in >= 15) k++;  // skip scalar M slot if present
    const float* n1g    = (const float*)d_in[k++];
    const float* n1b    = (const float*)d_in[k++];
    const float* qkv_w  = (const float*)d_in[k++];
    const float* qkv_b  = (const float*)d_in[k++];
    const float* proj_w = (const float*)d_in[k++];
    const float* proj_b = (const float*)d_in[k++];
    const float* n2g    = (const float*)d_in[k++];
    const float* n2b    = (const float*)d_in[k++];
    const float* fc1_w  = (const float*)d_in[k++];
    const float* fc1_b  = (const float*)d_in[k++];
    const float* fc2_w  = (const float*)d_in[k++];
    const float* fc2_b  = (const float*)d_in[k++];

    float* X = (float*)d_out;

    __half *p_xh, *p_qkv, *p_attn, *p_h2, *p_hid, *p_wh;
    float *p_h;
    int *p_rowmap;
    cudaGetSymbolAddress((void**)&p_xh,     g_xh);
    cudaGetSymbolAddress((void**)&p_qkv,    g_qkv);
    cudaGetSymbolAddress((void**)&p_attn,   g_attn);
    cudaGetSymbolAddress((void**)&p_h,      g_h);
    cudaGetSymbolAddress((void**)&p_h2,     g_h2);
    cudaGetSymbolAddress((void**)&p_hid,    g_hid);
    cudaGetSymbolAddress((void**)&p_wh,     g_wh);
    cudaGetSymbolAddress((void**)&p_rowmap, g_rowmap);

    cudaFuncSetAttribute(gemm_h<0, true>,  cudaFuncAttributeMaxDynamicSharedMemorySize, SMEM_H);
    cudaFuncSetAttribute(gemm_h<1, true>,  cudaFuncAttributeMaxDynamicSharedMemorySize, SMEM_H);
    cudaFuncSetAttribute(gemm_h<2, false>, cudaFuncAttributeMaxDynamicSharedMemorySize, SMEM_H);

    // 0) transpose + fp16-round weights -> [N,K] K-major
    wtrans_kernel<<<(DIM*QKVC + 255)/256, 256>>>(qkv_w,  p_wh + WOFF_QKV,  DIM, QKVC);
    wtrans_kernel<<<(DIM*DIM  + 255)/256, 256>>>(proj_w, p_wh + WOFF_PROJ, DIM, DIM);
    wtrans_kernel<<<(DIM*HID  + 255)/256, 256>>>(fc1_w,  p_wh + WOFF_FC1,  DIM, HID);
    wtrans_kernel<<<(HID*DIM  + 255)/256, 256>>>(fc2_w,  p_wh + WOFF_FC2,  HID, DIM);

    // 1) LayerNorm1: exact fp32 -> d_out, half copy -> g_xh
    ln_kernel<true><<<ROWS_ALL / 8, 256>>>(x, X, p_xh, n1g, n1b, ROWS_ALL);

    // 2) Row map
    rowmap_kernel<<<TOK / 256, 256>>>(index);

    // 3) QKV: gather(g_xh) @ qkv_w + b -> g_qkv (half)  [131072 x 768]
    gemm_h<0, true><<<dim3(QKVC/128, TOK/128), 256, SMEM_H>>>(
        p_xh, p_rowmap, p_wh + WOFF_QKV, qkv_b, p_qkv, nullptr, nullptr, nullptr, QKVC, DIM);

    // 4) Attention -> g_attn (half)
    attn_kernel<<<M_ACT * H, 64>>>(p_qkv, p_attn);

    // 5) Proj + shortcut(gathered fp32 X) -> g_h (fp32)
    gemm_h<2, false><<<dim3(DIM/128, TOK/128), 256, SMEM_H>>>(
        p_attn, nullptr, p_wh + WOFF_PROJ, proj_b, p_h, nullptr, X, p_rowmap, DIM, DIM);

    // 6) LayerNorm2: g_h -> g_h2 (half only)
    ln_kernel<false><<<TOK / 8, 256>>>(p_h, nullptr, p_h2, n2g, n2b, TOK);

    // 7) FC1 + GELU -> g_hid (half)  [131072 x 1024]
    gemm_h<1, true><<<dim3(HID/128, TOK/128), 256, SMEM_H>>>(
        p_h2, nullptr, p_wh + WOFF_FC1, fc1_b, p_hid, nullptr, nullptr, nullptr, HID, DIM);

    // 8) FC2 + residual(g_h fp32), scatter fp32 rows into d_out
    gemm_h<2, false><<<dim3(DIM/128, TOK/128), 256, SMEM_H>>>(
        p_hid, nullptr, p_wh + WOFF_FC2, fc2_b, X, p_rowmap, p_h, nullptr, DIM, HID);

    (void)in_sizes; (void)out_size;
}

// round 15
// speedup vs baseline: 3.8433x; 1.2158x over previous
#include <cuda_runtime.h>
#include <cuda_fp16.h>
#include <math.h>
#include <stdint.h>

// ---------------------------------------------------------------------------
// Problem constants (fixed shapes)
// ---------------------------------------------------------------------------
#define NWIN   4096
#define W      64
#define DIM    256
#define H      8
#define DH     32
#define HID    1024
#define M_ACT  2048
#define TOK    (M_ACT * W)        // 131072 active tokens
#define ROWS_ALL (NWIN * W)       // 262144 total rows
#define QKVC   (3 * DIM)          // 768

// ---------------------------------------------------------------------------
// Scratch (device globals; allocation inside kernel_launch is forbidden)
// ---------------------------------------------------------------------------
__device__ __half g_xh  [(size_t)ROWS_ALL * DIM];  // LN1 out, half (GEMM A)
__device__ __half g_qkv [(size_t)TOK * QKVC];
__device__ __half g_attn[(size_t)TOK * DIM];
__device__ float  g_h   [(size_t)TOK * DIM];       // residual stream, fp32
__device__ __half g_h2  [(size_t)TOK * DIM];
__device__ __half g_hid [(size_t)TOK * HID];
__device__ int    g_rowmap[TOK];

// transposed + fp16-rounded weights, [N, K] K-major, concatenated
#define WOFF_QKV  0
#define WOFF_PROJ (DIM * QKVC)
#define WOFF_FC1  (WOFF_PROJ + DIM * DIM)
#define WOFF_FC2  (WOFF_FC1 + DIM * HID)
#define WTOTAL    (WOFF_FC2 + HID * DIM)
__device__ __half g_wh[WTOTAL];

// ---------------------------------------------------------------------------
// helpers
// ---------------------------------------------------------------------------
__device__ __forceinline__ uint32_t h2u(half2 h) {
    return *reinterpret_cast<uint32_t*>(&h);
}

// ---------------------------------------------------------------------------
// Weight transpose + fp16 round: dst[n*K + k] = (half)src[k*N + n]
// ---------------------------------------------------------------------------
__global__ void wtrans_kernel(const float* __restrict__ src,
                              __half* __restrict__ dst, int K, int N)
{
    int i = blockIdx.x * blockDim.x + threadIdx.x;
    if (i < K * N) {
        int n = i / K, k = i - n * K;
        dst[i] = __float2half_rn(src[(size_t)k * N + n]);
    }
}

// ---------------------------------------------------------------------------
// Row map
// ---------------------------------------------------------------------------
__global__ void rowmap_kernel(const int* __restrict__ index) {
    int t = blockIdx.x * blockDim.x + threadIdx.x;
    if (t < TOK) g_rowmap[t] = index[t >> 6] * W + (t & (W - 1));
}

// ---------------------------------------------------------------------------
// LayerNorm (one warp per row). Writes optional fp32 stream + half stream.
// ---------------------------------------------------------------------------
template<bool WRITE_F32>
__global__ __launch_bounds__(256)
void ln_kernel(const float* __restrict__ in, float* __restrict__ outf,
               __half* __restrict__ outh,
               const float* __restrict__ gam, const float* __restrict__ bet,
               int nrows)
{
    int warp = threadIdx.x >> 5;
    int lane = threadIdx.x & 31;
    int row  = blockIdx.x * 8 + warp;
    if (row >= nrows) return;

    const float* p = in + (size_t)row * DIM;
    float4 v0 = *(const float4*)(p + lane * 4);
    float4 v1 = *(const float4*)(p + 128 + lane * 4);

    float s = v0.x + v0.y + v0.z + v0.w + v1.x + v1.y + v1.z + v1.w;
    #pragma unroll
    for (int o = 16; o > 0; o >>= 1) s += __shfl_xor_sync(0xffffffffu, s, o);
    float mu = s * (1.0f / 256.0f);

    float d0 = v0.x - mu, d1 = v0.y - mu, d2 = v0.z - mu, d3 = v0.w - mu;
    float d4 = v1.x - mu, d5 = v1.y - mu, d6 = v1.z - mu, d7 = v1.w - mu;
    float vs = d0*d0 + d1*d1 + d2*d2 + d3*d3 + d4*d4 + d5*d5 + d6*d6 + d7*d7;
    #pragma unroll
    for (int o = 16; o > 0; o >>= 1) vs += __shfl_xor_sync(0xffffffffu, vs, o);
    float inv = rsqrtf(vs * (1.0f / 256.0f) + 1e-5f);

    float4 g0 = *(const float4*)(gam + lane * 4);
    float4 g1 = *(const float4*)(gam + 128 + lane * 4);
    float4 b0 = *(const float4*)(bet + lane * 4);
    float4 b1 = *(const float4*)(bet + 128 + lane * 4);

    float4 o0, o1;
    o0.x = d0 * inv * g0.x + b0.x;  o0.y = d1 * inv * g0.y + b0.y;
    o0.z = d2 * inv * g0.z + b0.z;  o0.w = d3 * inv * g0.w + b0.w;
    o1.x = d4 * inv * g1.x + b1.x;  o1.y = d5 * inv * g1.y + b1.y;
    o1.z = d6 * inv * g1.z + b1.z;  o1.w = d7 * inv * g1.w + b1.w;

    if (WRITE_F32) {
        float* q = outf + (size_t)row * DIM;
        *(float4*)(q + lane * 4) = o0;
        *(float4*)(q + 128 + lane * 4) = o1;
    }
    __half* qh = outh + (size_t)row * DIM;
    *(half2*)(qh + lane * 4)           = __floats2half2_rn(o0.x, o0.y);
    *(half2*)(qh + lane * 4 + 2)       = __floats2half2_rn(o0.z, o0.w);
    *(half2*)(qh + 128 + lane * 4)     = __floats2half2_rn(o1.x, o1.y);
    *(half2*)(qh + 128 + lane * 4 + 2) = __floats2half2_rn(o1.z, o1.w);
}

// ---------------------------------------------------------------------------
// Common mma/ldmatrix helpers
// ---------------------------------------------------------------------------
__device__ __forceinline__ void cp_async16s(uint32_t smem, const void* gmem) {
    asm volatile("cp.async.cg.shared.global [%0], [%1], 16;\n" :: "r"(smem), "l"(gmem));
}
__device__ __forceinline__ void cp_commit() { asm volatile("cp.async.commit_group;\n"); }
template<int N> __device__ __forceinline__ void cp_wait() {
    asm volatile("cp.async.wait_group %0;\n" :: "n"(N));
}

__device__ __forceinline__ void ldmx4(uint32_t* r, uint32_t addr) {
    asm volatile("ldmatrix.sync.aligned.m8n8.x4.shared.b16 {%0,%1,%2,%3}, [%4];"
                 : "=r"(r[0]), "=r"(r[1]), "=r"(r[2]), "=r"(r[3]) : "r"(addr));
}

__device__ __forceinline__ void mma_f16(float* c, const uint32_t* a, const uint32_t* b) {
    asm volatile(
        "mma.sync.aligned.m16n8k16.row.col.f32.f16.f16.f32 "
        "{%0,%1,%2,%3},{%4,%5,%6,%7},{%8,%9},{%0,%1,%2,%3};\n"
        : "+f"(c[0]), "+f"(c[1]), "+f"(c[2]), "+f"(c[3])
        : "r"(a[0]), "r"(a[1]), "r"(a[2]), "r"(a[3]), "r"(b[0]), "r"(b[1]));
}

// ---------------------------------------------------------------------------
// fp16 tensor-core GEMM (unchanged from R13 — passing)
// ---------------------------------------------------------------------------
#define NSTG 4
#define BKH 32
#define ASTRH 40
#define STAGEB (128 * ASTRH * 2)
#define SMEM_H (2 * NSTG * STAGEB)    // 81920 bytes

template<int EPI, bool OUTH>
__global__ __launch_bounds__(256)
void gemm_h(const __half* __restrict__ A, const int* __restrict__ rowmapA,
            const __half* __restrict__ Bt, const float* __restrict__ bias,
            void* __restrict__ Cv, const int* __restrict__ rowmapC,
            const float* __restrict__ Res, const int* __restrict__ rowmapRes,
            int Ncols, int K)
{
    extern __shared__ __align__(16) char dyn[];
    const uint32_t sbase = (uint32_t)__cvta_generic_to_shared(dyn);

    const int tid = threadIdx.x;
    const int rowBase = blockIdx.y * 128;
    const int colBase = blockIdx.x * 128;

    const int r  = tid >> 1;
    const int c0 = (tid & 1) * 2;
    const int gra = rowBase + r;
    const size_t arow = rowmapA ? (size_t)rowmapA[gra] : (size_t)gra;
    const __half* Ag = A + arow * (size_t)K;
    const __half* Bg = Bt + (size_t)(colBase + r) * K;
    const uint32_t sArow = (uint32_t)(r * (ASTRH * 2));

    const int warp  = tid >> 5;
    const int lane  = tid & 31;
    const int warpM = warp >> 1;
    const int warpN = warp & 1;
    const int grp   = lane >> 2;
    const int tig   = lane & 3;

    float acc[2][8][4];
    #pragma unroll
    for (int mt = 0; mt < 2; mt++)
        #pragma unroll
        for (int nt = 0; nt < 8; nt++)
            #pragma unroll
            for (int j = 0; j < 4; j++) acc[mt][nt][j] = 0.0f;

    const int KT = K / BKH;

    auto issue = [&](int kt) {
        const int s = kt % NSTG;
        const uint32_t aB = sbase + s * STAGEB;
        const uint32_t bB = sbase + NSTG * STAGEB + s * STAGEB;
        const __half* ag = Ag + kt * BKH;
        const __half* bg = Bg + kt * BKH;
        cp_async16s(aB + sArow + c0 * 16,       ag + c0 * 8);
        cp_async16s(aB + sArow + (c0 + 1) * 16, ag + (c0 + 1) * 8);
        cp_async16s(bB + sArow + c0 * 16,       bg + c0 * 8);
        cp_async16s(bB + sArow + (c0 + 1) * 16, bg + (c0 + 1) * 8);
        cp_commit();
    };

    issue(0);
    if (KT > 1) issue(1);
    if (KT > 2) issue(2);

    const uint32_t aLdRow = (uint32_t)(warpM * 32 + (lane & 15));
    const uint32_t aLdCol = (uint32_t)((lane >> 4) * 8);
    const uint32_t bLdRow0 = (uint32_t)(warpN * 64 + (lane & 7) + (lane >> 4) * 8);
    const uint32_t bLdCol = (uint32_t)(((lane >> 3) & 1) * 8);

    for (int kt = 0; kt < KT; kt++) {
        const int rem = KT - 1 - kt;
        if (rem >= 2)      cp_wait<2>();
        else if (rem == 1) cp_wait<1>();
        else               cp_wait<0>();
        __syncthreads();
        if (kt + 3 < KT) issue(kt + 3);

        const int s = kt % NSTG;
        const uint32_t aB = sbase + s * STAGEB;
        const uint32_t bB = sbase + NSTG * STAGEB + s * STAGEB;

        #pragma unroll
        for (int ks = 0; ks < 2; ks++) {
            const uint32_t kb = (uint32_t)(ks * 16);

            uint32_t afr[2][4];
            #pragma unroll
            for (int mt = 0; mt < 2; mt++) {
                uint32_t addr = aB + ((aLdRow + mt * 16) * ASTRH + kb + aLdCol) * 2;
                ldmx4(afr[mt], addr);
            }
            uint32_t bfr[8][2];
            #pragma unroll
            for (int np = 0; np < 4; np++) {
                uint32_t t[4];
                uint32_t addr = bB + ((bLdRow0 + np * 16) * ASTRH + kb + bLdCol) * 2;
                ldmx4(t, addr);
                bfr[2 * np][0]     = t[0];
                bfr[2 * np][1]     = t[1];
                bfr[2 * np + 1][0] = t[2];
                bfr[2 * np + 1][1] = t[3];
            }
            #pragma unroll
            for (int mt = 0; mt < 2; mt++)
                #pragma unroll
                for (int nt = 0; nt < 8; nt++)
                    mma_f16(acc[mt][nt], afr[mt], bfr[nt]);
        }
        __syncthreads();
    }

    #pragma unroll
    for (int mt = 0; mt < 2; mt++) {
        #pragma unroll
        for (int hf = 0; hf < 2; hf++) {
            const int gr = rowBase + warpM * 32 + mt * 16 + grp + hf * 8;
            const size_t crow = rowmapC ? (size_t)rowmapC[gr] : (size_t)gr;
            const float* Rp = nullptr;
            if (EPI == 2) {
                const size_t rrow = rowmapRes ? (size_t)rowmapRes[gr] : (size_t)gr;
                Rp = Res + rrow * (size_t)Ncols;
            }
            #pragma unroll
            for (int nt = 0; nt < 8; nt++) {
                const int col = colBase + warpN * 64 + nt * 8 + 2 * tig;
                float v0 = acc[mt][nt][hf * 2 + 0] + __ldg(bias + col);
                float v1 = acc[mt][nt][hf * 2 + 1] + __ldg(bias + col + 1);
                if (EPI == 1) {
                    v0 = 0.5f * v0 * (1.0f + erff(v0 * 0.70710678118654752f));
                    v1 = 0.5f * v1 * (1.0f + erff(v1 * 0.70710678118654752f));
                }
                if (EPI == 2) { v0 += Rp[col]; v1 += Rp[col + 1]; }
                if (OUTH) {
                    __half* Cp = (__half*)Cv + crow * (size_t)Ncols;
                    *(half2*)(Cp + col) = __floats2half2_rn(v0, v1);
                } else {
                    float* Cp = (float*)Cv + crow * (size_t)Ncols;
                    *(float2*)(Cp + col) = make_float2(v0, v1);
                }
            }
        }
    }
}

// ---------------------------------------------------------------------------
// Tensor-core attention.
// CTA = 256 threads = 8 warps = 4 window-heads (2 warps each: 32 q-rows/warp).
// Per window-head smem: Q[64][40]h, K[64][40]h (row-major [seq,d]),
// Vt[32][72]h (transposed [d,seq]). All strides conflict-free for ldmatrix.
// ---------------------------------------------------------------------------
#define AQS 2560          // 64*40 halves per wh (Q or K)
#define AVS 2304          // 32*72 halves per wh (Vt)
#define SMEM_ATTN ((4 * (2 * AQS + AVS)) * 2)   // 59392 bytes

__global__ __launch_bounds__(256)
void attn_mma_kernel(const __half* __restrict__ qkv, __half* __restrict__ attn_out)
{
    extern __shared__ __align__(16) char dynb[];
    __half* sm = (__half*)dynb;

    const int tid = threadIdx.x;

    // ---- cooperative staging of 4 window-heads ----
    for (int i = tid; i < 4096; i += 256) {
        const int widx = i >> 10;
        const int row  = (i >> 4) & 63;
        const int dp   = (i & 15) * 2;
        const int whg  = blockIdx.x * 4 + widx;
        const int m = whg >> 3, h = whg & 7;
        const __half* rp = qkv + ((size_t)m * W + row) * QKVC + h * (3 * DH);
        half2 q2 = *(const half2*)(rp + dp);
        half2 k2 = *(const half2*)(rp + DH + dp);
        half2 v2 = *(const half2*)(rp + 2 * DH + dp);
        *(half2*)(sm + widx * AQS + row * 40 + dp)            = q2;
        *(half2*)(sm + 4 * AQS + widx * AQS + row * 40 + dp)  = k2;
        __half* vt = sm + 8 * AQS + widx * AVS;
        vt[(dp)     * 72 + row] = __low2half(v2);
        vt[(dp + 1) * 72 + row] = __high2half(v2);
    }
    __syncthreads();

    const int warp = tid >> 5;
    const int lane = tid & 31;
    const int widx = warp >> 1;
    const int p    = warp & 1;          // which 32-row half of the window
    const int whg  = blockIdx.x * 4 + widx;
    const int m = whg >> 3, h = whg & 7;

    const uint32_t sQ = (uint32_t)__cvta_generic_to_shared(sm + widx * AQS);
    const uint32_t sK = (uint32_t)__cvta_generic_to_shared(sm + 4 * AQS + widx * AQS);
    const uint32_t sV = (uint32_t)__cvta_generic_to_shared(sm + 8 * AQS + widx * AVS);

    const int grp = lane >> 2;
    const int tig = lane & 3;
    const uint32_t aRow = (uint32_t)(p * 32 + (lane & 15));
    const uint32_t aCol = (uint32_t)((lane >> 4) * 8);
    const uint32_t bRow = (uint32_t)((lane & 7) + (lane >> 4) * 8);
    const uint32_t bCol = (uint32_t)(((lane >> 3) & 1) * 8);

    // ---- Q fragments (2 m-tiles x 2 k-steps) ----
    uint32_t qf[2][2][4];
    #pragma unroll
    for (int mt = 0; mt < 2; mt++)
        #pragma unroll
        for (int ks = 0; ks < 2; ks++)
            ldmx4(qf[mt][ks], sQ + ((aRow + mt * 16) * 40 + ks * 16 + aCol) * 2);

    // ---- S = Q @ K^T : 32x64 per warp ----
    float sacc[2][8][4];
    #pragma unroll
    for (int mt = 0; mt < 2; mt++)
        #pragma unroll
        for (int nt = 0; nt < 8; nt++)
            #pragma unroll
            for (int j = 0; j < 4; j++) sacc[mt][nt][j] = 0.0f;

    #pragma unroll
    for (int ks = 0; ks < 2; ks++) {
        uint32_t bf[8][2];
        #pragma unroll
        for (int np = 0; np < 4; np++) {
            uint32_t t[4];
            ldmx4(t, sK + ((bRow + np * 16) * 40 + ks * 16 + bCol) * 2);
            bf[2 * np][0] = t[0]; bf[2 * np][1] = t[1];
            bf[2 * np + 1][0] = t[2]; bf[2 * np + 1][1] = t[3];
        }
        #pragma unroll
        for (int mt = 0; mt < 2; mt++)
            #pragma unroll
            for (int nt = 0; nt < 8; nt++)
                mma_f16(sacc[mt][nt], qf[mt][ks], bf[nt]);
    }

    // ---- softmax over k (row spans tig lanes x 8 n-tiles x 2 cols) ----
    const float scale = 0.17677669529663687f; // 1/sqrt(32)
    #pragma unroll
    for (int mt = 0; mt < 2; mt++) {
        #pragma unroll
        for (int rh = 0; rh < 2; rh++) {
            float mx = -1e30f;
            #pragma unroll
            for (int nt = 0; nt < 8; nt++)
                mx = fmaxf(mx, fmaxf(sacc[mt][nt][rh * 2], sacc[mt][nt][rh * 2 + 1]));
            mx = fmaxf(mx, __shfl_xor_sync(0xffffffffu, mx, 1));
            mx = fmaxf(mx, __shfl_xor_sync(0xffffffffu, mx, 2));
            float sum = 0.0f;
            #pragma unroll
            for (int nt = 0; nt < 8; nt++) {
                float e0 = __expf((sacc[mt][nt][rh * 2]     - mx) * scale);
                float e1 = __expf((sacc[mt][nt][rh * 2 + 1] - mx) * scale);
                sacc[mt][nt][rh * 2] = e0; sacc[mt][nt][rh * 2 + 1] = e1;
                sum += e0 + e1;
            }
            sum += __shfl_xor_sync(0xffffffffu, sum, 1);
            sum += __shfl_xor_sync(0xffffffffu, sum, 2);
            const float inv = 1.0f / sum;
            #pragma unroll
            for (int nt = 0; nt < 8; nt++) {
                sacc[mt][nt][rh * 2]     *= inv;
                sacc[mt][nt][rh * 2 + 1] *= inv;
            }
        }
    }

    // ---- pack P into A fragments (C-frag layout == A-frag layout) ----
    uint32_t pa[2][4][4];
    #pragma unroll
    for (int mt = 0; mt < 2; mt++)
        #pragma unroll
        for (int kt = 0; kt < 4; kt++) {
            pa[mt][kt][0] = h2u(__floats2half2_rn(sacc[mt][2*kt][0],   sacc[mt][2*kt][1]));
            pa[mt][kt][1] = h2u(__floats2half2_rn(sacc[mt][2*kt][2],   sacc[mt][2*kt][3]));
            pa[mt][kt][2] = h2u(__floats2half2_rn(sacc[mt][2*kt+1][0], sacc[mt][2*kt+1][1]));
            pa[mt][kt][3] = h2u(__floats2half2_rn(sacc[mt][2*kt+1][2], sacc[mt][2*kt+1][3]));
        }

    // ---- O = P @ V : 32x32 per warp (B = Vt [d, seq] row-major) ----
    float oacc[2][4][4];
    #pragma unroll
    for (int mt = 0; mt < 2; mt++)
        #pragma unroll
        for (int nt = 0; nt < 4; nt++)
            #pragma unroll
            for (int j = 0; j < 4; j++) oacc[mt][nt][j] = 0.0f;

    #pragma unroll
    for (int kt = 0; kt < 4; kt++) {
        uint32_t vf[4][2];
        #pragma unroll
        for (int np = 0; np < 2; np++) {
            uint32_t t[4];
            ldmx4(t, sV + ((bRow + np * 16) * 72 + kt * 16 + bCol) * 2);
            vf[2 * np][0] = t[0]; vf[2 * np][1] = t[1];
            vf[2 * np + 1][0] = t[2]; vf[2 * np + 1][1] = t[3];
        }
        #pragma unroll
        for (int mt = 0; mt < 2; mt++)
            #pragma unroll
            for (int nt = 0; nt < 4; nt++)
                mma_f16(oacc[mt][nt], pa[mt][kt], vf[nt]);
    }

    // ---- write O ----
    __half* ob = attn_out + (size_t)m * W * DIM + h * DH;
    #pragma unroll
    for (int mt = 0; mt < 2; mt++) {
        const int row0 = p * 32 + mt * 16 + grp;
        #pragma unroll
        for (int nt = 0; nt < 4; nt++) {
            const int col = nt * 8 + 2 * tig;
            *(half2*)(ob + (size_t)row0 * DIM + col) =
                __floats2half2_rn(oacc[mt][nt][0], oacc[mt][nt][1]);
            *(half2*)(ob + (size_t)(row0 + 8) * DIM + col) =
                __floats2half2_rn(oacc[mt][nt][2], oacc[mt][nt][3]);
        }
    }
}

// ---------------------------------------------------------------------------
// Launch
// ---------------------------------------------------------------------------
extern "C" void kernel_launch(void* const* d_in, const int* in_sizes, int n_in,
                              void* d_out, int out_size)
{
    int k = 0;
    const float* x      = (const float*)d_in[k++];
    const int*   index  = (const int*)  d_in[k++];
    if (n_in >= 15) k++;  // skip scalar M slot if present
    const float* n1g    = (const float*)d_in[k++];
    const float* n1b    = (const float*)d_in[k++];
    const float* qkv_w  = (const float*)d_in[k++];
    const float* qkv_b  = (const float*)d_in[k++];
    const float* proj_w = (const float*)d_in[k++];
    const float* proj_b = (const float*)d_in[k++];
    const float* n2g    = (const float*)d_in[k++];
    const float* n2b    = (const float*)d_in[k++];
    const float* fc1_w  = (const float*)d_in[k++];
    const float* fc1_b  = (const float*)d_in[k++];
    const float* fc2_w  = (const float*)d_in[k++];
    const float* fc2_b  = (const float*)d_in[k++];

    float* X = (float*)d_out;

    __half *p_xh, *p_qkv, *p_attn, *p_h2, *p_hid, *p_wh;
    float *p_h;
    int *p_rowmap;
    cudaGetSymbolAddress((void**)&p_xh,     g_xh);
    cudaGetSymbolAddress((void**)&p_qkv,    g_qkv);
    cudaGetSymbolAddress((void**)&p_attn,   g_attn);
    cudaGetSymbolAddress((void**)&p_h,      g_h);
    cudaGetSymbolAddress((void**)&p_h2,     g_h2);
    cudaGetSymbolAddress((void**)&p_hid,    g_hid);
    cudaGetSymbolAddress((void**)&p_wh,     g_wh);
    cudaGetSymbolAddress((void**)&p_rowmap, g_rowmap);

    cudaFuncSetAttribute(gemm_h<0, true>,  cudaFuncAttributeMaxDynamicSharedMemorySize, SMEM_H);
    cudaFuncSetAttribute(gemm_h<1, true>,  cudaFuncAttributeMaxDynamicSharedMemorySize, SMEM_H);
    cudaFuncSetAttribute(gemm_h<2, false>, cudaFuncAttributeMaxDynamicSharedMemorySize, SMEM_H);
    cudaFuncSetAttribute(attn_mma_kernel,  cudaFuncAttributeMaxDynamicSharedMemorySize, SMEM_ATTN);

    // 0) transpose + fp16-round weights -> [N,K] K-major
    wtrans_kernel<<<(DIM*QKVC + 255)/256, 256>>>(qkv_w,  p_wh + WOFF_QKV,  DIM, QKVC);
    wtrans_kernel<<<(DIM*DIM  + 255)/256, 256>>>(proj_w, p_wh + WOFF_PROJ, DIM, DIM);
    wtrans_kernel<<<(DIM*HID  + 255)/256, 256>>>(fc1_w,  p_wh + WOFF_FC1,  DIM, HID);
    wtrans_kernel<<<(HID*DIM  + 255)/256, 256>>>(fc2_w,  p_wh + WOFF_FC2,  HID, DIM);

    // 1) LayerNorm1: exact fp32 -> d_out, half copy -> g_xh
    ln_kernel<true><<<ROWS_ALL / 8, 256>>>(x, X, p_xh, n1g, n1b, ROWS_ALL);

    // 2) Row map
    rowmap_kernel<<<TOK / 256, 256>>>(index);

    // 3) QKV: gather(g_xh) @ qkv_w + b -> g_qkv (half)  [131072 x 768]
    gemm_h<0, true><<<dim3(QKVC/128, TOK/128), 256, SMEM_H>>>(
        p_xh, p_rowmap, p_wh + WOFF_QKV, qkv_b, p_qkv, nullptr, nullptr, nullptr, QKVC, DIM);

    // 4) Attention (tensor-core) -> g_attn (half)
    attn_mma_kernel<<<M_ACT * H / 4, 256, SMEM_ATTN>>>(p_qkv, p_attn);

    // 5) Proj + shortcut(gathered fp32 X) -> g_h (fp32)
    gemm_h<2, false><<<dim3(DIM/128, TOK/128), 256, SMEM_H>>>(
        p_attn, nullptr, p_wh + WOFF_PROJ, proj_b, p_h, nullptr, X, p_rowmap, DIM, DIM);

    // 6) LayerNorm2: g_h -> g_h2 (half only)
    ln_kernel<false><<<TOK / 8, 256>>>(p_h, nullptr, p_h2, n2g, n2b, TOK);

    // 7) FC1 + GELU -> g_hid (half)  [131072 x 1024]
    gemm_h<1, true><<<dim3(HID/128, TOK/128), 256, SMEM_H>>>(
        p_h2, nullptr, p_wh + WOFF_FC1, fc1_b, p_hid, nullptr, nullptr, nullptr, HID, DIM);

    // 8) FC2 + residual(g_h fp32), scatter fp32 rows into d_out
    gemm_h<2, false><<<dim3(DIM/128, TOK/128), 256, SMEM_H>>>(
        p_hid, nullptr, p_wh + WOFF_FC2, fc2_b, X, p_rowmap, p_h, nullptr, DIM, HID);

    (void)in_sizes; (void)out_size;
}